// round 12
// baseline (speedup 1.0000x reference)
#include <cuda_runtime.h>
#include <cuda_bf16.h>
#include <stdint.h>
#include <math.h>

#define B_    2
#define S_    2048
#define D_    1536
#define QKV3  4608
#define HD_   128
#define NFULL 6
#define NLOCAL 4
#define HWIN  32
#define SCALE 0.08838834764831845f   // 1/sqrt(128)
#define KDIM  1536
#define MROWS 4096                   // B_*S_

// ---------------------------------------------------------------------------
// Scratch (device globals: allocation-free)
// ---------------------------------------------------------------------------
__device__ __nv_bfloat16 g_qkvh[(size_t)MROWS * QKV3];
__device__ __nv_bfloat16 g_qkvl[(size_t)MROWS * QKV3];
__device__ __nv_bfloat16 g_Xh[(size_t)MROWS * KDIM];
__device__ __nv_bfloat16 g_Xl[(size_t)MROWS * KDIM];
__device__ __nv_bfloat16 g_A2h[(size_t)MROWS * KDIM];   // attn output hi
__device__ __nv_bfloat16 g_A2l[(size_t)MROWS * KDIM];   // attn output lo
__device__ __nv_bfloat16 g_Wqh[(size_t)QKV3 * KDIM];    // transposed [N][K]
__device__ __nv_bfloat16 g_Wql[(size_t)QKV3 * KDIM];
__device__ __nv_bfloat16 g_Woh[(size_t)D_ * KDIM];
__device__ __nv_bfloat16 g_Wol[(size_t)D_ * KDIM];

// ---------------------------------------------------------------------------
// PTX helpers (sm_80-baseline: legal on plain compute_103 target)
// ---------------------------------------------------------------------------
__device__ __forceinline__ uint32_t smem_u32(const void* p) {
    uint32_t a;
    asm("{ .reg .u64 t; cvta.to.shared.u64 t, %1; cvt.u32.u64 %0, t; }"
        : "=r"(a) : "l"(p));
    return a;
}
__device__ __forceinline__ void cp16(uint32_t d, const void* s) {
    asm volatile("cp.async.cg.shared.global [%0], [%1], 16;" :: "r"(d), "l"(s));
}
#define CP_COMMIT() asm volatile("cp.async.commit_group;" ::: "memory")

__device__ __forceinline__ void ldm_x4(uint32_t* r, uint32_t addr) {
    asm volatile("ldmatrix.sync.aligned.m8n8.x4.shared.b16 {%0,%1,%2,%3}, [%4];"
                 : "=r"(r[0]), "=r"(r[1]), "=r"(r[2]), "=r"(r[3]) : "r"(addr));
}
__device__ __forceinline__ void ldm_x2(uint32_t* r, uint32_t addr) {
    asm volatile("ldmatrix.sync.aligned.m8n8.x2.shared.b16 {%0,%1}, [%2];"
                 : "=r"(r[0]), "=r"(r[1]) : "r"(addr));
}
__device__ __forceinline__ void ldm_x2t(uint32_t* r, uint32_t addr) {
    asm volatile("ldmatrix.sync.aligned.m8n8.x2.trans.shared.b16 {%0,%1}, [%2];"
                 : "=r"(r[0]), "=r"(r[1]) : "r"(addr));
}
__device__ __forceinline__ void mma16816(float* c, const uint32_t* a,
                                         const uint32_t* b) {
    asm volatile(
        "mma.sync.aligned.m16n8k16.row.col.f32.bf16.bf16.f32 "
        "{%0,%1,%2,%3}, {%4,%5,%6,%7}, {%8,%9}, {%0,%1,%2,%3};"
        : "+f"(c[0]), "+f"(c[1]), "+f"(c[2]), "+f"(c[3])
        : "r"(a[0]), "r"(a[1]), "r"(a[2]), "r"(a[3]), "r"(b[0]), "r"(b[1]));
}
// pack two f32 -> bf16x2 (first arg -> low half / lower address)
__device__ __forceinline__ uint32_t packbf(float lo, float hi) {
    uint32_t r;
    asm("cvt.rn.bf16x2.f32 %0, %1, %2;" : "=r"(r) : "f"(hi), "f"(lo));
    return r;
}
__device__ __forceinline__ float bf2f(float p) {
    return __bfloat162float(__float2bfloat16(p));
}

// ---------------------------------------------------------------------------
// Split kernels: fp32 -> (hi, lo) bf16
// ---------------------------------------------------------------------------
__global__ __launch_bounds__(256) void k_split(
    const float* __restrict__ in, __nv_bfloat16* __restrict__ hi,
    __nv_bfloat16* __restrict__ lo, int n)
{
    int i = (blockIdx.x * 256 + threadIdx.x) * 4;
    if (i >= n) return;
    float4 v = *(const float4*)(in + i);
    uint32_t* hp = (uint32_t*)(hi + i);
    uint32_t* lp = (uint32_t*)(lo + i);
    hp[0] = packbf(v.x, v.y);
    hp[1] = packbf(v.z, v.w);
    lp[0] = packbf(v.x - bf2f(v.x), v.y - bf2f(v.y));
    lp[1] = packbf(v.z - bf2f(v.z), v.w - bf2f(v.w));
}

// in: fp32 [K,N] -> out hi/lo bf16 [N,K] (transposed)
__global__ __launch_bounds__(256) void k_splitT(
    const float* __restrict__ in, __nv_bfloat16* __restrict__ hi,
    __nv_bfloat16* __restrict__ lo, int Kd, int Nd)
{
    __shared__ float t[32][33];
    const int n0 = blockIdx.x * 32, k0 = blockIdx.y * 32;
    const int tx = threadIdx.x & 31, ty = threadIdx.x >> 5;
#pragma unroll
    for (int j = 0; j < 32; j += 8)
        t[ty + j][tx] = in[(size_t)(k0 + ty + j) * Nd + n0 + tx];
    __syncthreads();
#pragma unroll
    for (int j = 0; j < 32; j += 8) {
        float v = t[tx][ty + j];
        __nv_bfloat16 h = __float2bfloat16(v);
        size_t o = (size_t)(n0 + ty + j) * Kd + k0 + tx;
        hi[o] = h;
        lo[o] = __float2bfloat16(v - __bfloat162float(h));
    }
}

// ---------------------------------------------------------------------------
// Fixup: compute qkv (bf16 hi/lo) for the 4 global-head K/V column tiles
// skipped by the main GEMM, at the only 4 rows ever read (token 0 and S-1
// of each batch). 16 blocks x 128 threads; exact fp32 dot products.
// ---------------------------------------------------------------------------
__global__ __launch_bounds__(128) void fix_globalqkv(
    const float* __restrict__ x, const float* __restrict__ Wqkv,
    const float* __restrict__ bqkv,
    __nv_bfloat16* __restrict__ qkvh, __nv_bfloat16* __restrict__ qkvl)
{
    __shared__ float xs[KDIM];
    const int rows[4] = {0, S_ - 1, S_, 2 * S_ - 1};
    const int cols[4] = {2816, 2944, 4352, 4480};
    const int row = rows[blockIdx.x >> 2];
    const int c   = cols[blockIdx.x & 3] + threadIdx.x;

    for (int k = threadIdx.x; k < KDIM; k += 128)
        xs[k] = x[(size_t)row * KDIM + k];
    __syncthreads();

    float s = 0.f;
#pragma unroll 8
    for (int k = 0; k < KDIM; k++)
        s += xs[k] * Wqkv[(size_t)k * QKV3 + c];
    s += bqkv[c];

    const size_t o = (size_t)row * QKV3 + c;
    const __nv_bfloat16 h = __float2bfloat16(s);
    qkvh[o] = h;
    qkvl[o] = __float2bfloat16(s - __bfloat162float(h));
}

// ---------------------------------------------------------------------------
// HMMA GEMM: acc = Ah@Bh^T + Ah@Bl^T + Al@Bh^T + bias.
// mode 0: write fp32 C. mode 1: write bf16 hi/lo (Ch, Cl) and remap
// blockIdx.x to skip the 4 dead global-head column tiles {22,23,34,35}.
// 128x128 tile, BK=32, 8 warps (2x4), 2-stage cp.async, 2 CTAs/SM.
// ---------------------------------------------------------------------------
#define NCH    (KDIM / 32)          // 48
#define AROWB  80
#define TILEB  (128 * AROWB)        // 10240
#define STAGEB (4 * TILEB)          // 40960
#define GEMM_SMEM (2 * STAGEB)      // 81920

__global__ __launch_bounds__(256, 2) void gemm3t(
    const __nv_bfloat16* __restrict__ Ahg, const __nv_bfloat16* __restrict__ Alg,
    const __nv_bfloat16* __restrict__ Bhg, const __nv_bfloat16* __restrict__ Blg,
    const float* __restrict__ bias, float* __restrict__ C,
    __nv_bfloat16* __restrict__ Ch, __nv_bfloat16* __restrict__ Cl,
    int Ncols, int mode)
{
    extern __shared__ char smem[];
    const uint32_t sb = smem_u32(smem);
    const int tid  = threadIdx.x;
    const int wid  = tid >> 5;
    const int lane = tid & 31;
    const int warp_m = wid & 1;
    const int warp_n = wid >> 1;
    const int m0 = blockIdx.y * 128;
    int bx = blockIdx.x;
    if (mode == 1 && bx >= 22) bx += 2;   // skip dead tiles 22,23 (and 34,35 off-grid)
    const int n0 = bx * 128;

    const char* gAh = (const char*)(Ahg + (size_t)m0 * KDIM);
    const char* gAl = (const char*)(Alg + (size_t)m0 * KDIM);
    const char* gBh = (const char*)(Bhg + (size_t)n0 * KDIM);
    const char* gBl = (const char*)(Blg + (size_t)n0 * KDIM);

    float acc[4][4][4];
#pragma unroll
    for (int i = 0; i < 4; i++)
#pragma unroll
        for (int j = 0; j < 4; j++)
#pragma unroll
            for (int k = 0; k < 4; k++) acc[i][j][k] = 0.f;

#define LOAD_CHUNK(ch, stage) do {                                             \
        const uint32_t st = sb + (stage) * STAGEB;                             \
        const size_t kb = (size_t)(ch) * 64;                                   \
        _Pragma("unroll")                                                      \
        for (int t = 0; t < 8; t++) {                                          \
            const int u = tid + t * 256;                                       \
            const int tile = u >> 9;                                           \
            const int r = (u >> 2) & 127;                                      \
            const int c = u & 3;                                               \
            const char* g = (tile == 0) ? gAh : (tile == 1) ? gAl              \
                          : (tile == 2) ? gBh : gBl;                           \
            cp16(st + tile * TILEB + r * AROWB + c * 16,                       \
                 g + (size_t)r * (KDIM * 2) + kb + c * 16);                    \
        }                                                                      \
        CP_COMMIT();                                                           \
    } while (0)

    LOAD_CHUNK(0, 0);
    LOAD_CHUNK(1, 1);

    const int a_row  = warp_m * 64 + (lane & 15);
    const int a_koff = (lane >> 4) * 16;
    const int b_row  = warp_n * 32 + (lane & 7);
    const int b_koff = ((lane >> 3) & 1) * 16;

    for (int i = 0; i < NCH; i++) {
        const int p = i & 1;
        if (i + 1 < NCH) asm volatile("cp.async.wait_group 1;" ::: "memory");
        else             asm volatile("cp.async.wait_group 0;" ::: "memory");
        __syncthreads();

        const uint32_t sAh = sb + p * STAGEB;
        const uint32_t sAl = sAh + TILEB;
        const uint32_t sBh = sAh + 2 * TILEB;
        const uint32_t sBl = sAh + 3 * TILEB;

#pragma unroll
        for (int kk = 0; kk < 2; kk++) {
            uint32_t bh[4][2], bl[4][2];
#pragma unroll
            for (int nf = 0; nf < 4; nf++) {
                const uint32_t off = (b_row + nf * 8) * AROWB + kk * 32 + b_koff;
                ldm_x2(bh[nf], sBh + off);
                ldm_x2(bl[nf], sBl + off);
            }
#pragma unroll
            for (int mf = 0; mf < 4; mf++) {
                uint32_t ah[4], al[4];
                const uint32_t off = (a_row + mf * 16) * AROWB + kk * 32 + a_koff;
                ldm_x4(ah, sAh + off);
                ldm_x4(al, sAl + off);
#pragma unroll
                for (int nf = 0; nf < 4; nf++) mma16816(acc[mf][nf], ah, bh[nf]);
#pragma unroll
                for (int nf = 0; nf < 4; nf++) mma16816(acc[mf][nf], ah, bl[nf]);
#pragma unroll
                for (int nf = 0; nf < 4; nf++) mma16816(acc[mf][nf], al, bh[nf]);
            }
        }
        __syncthreads();
        if (i + 2 < NCH) LOAD_CHUNK(i + 2, p);
        else CP_COMMIT();
    }

    const int g_  = lane >> 2;
    const int tg  = lane & 3;
#pragma unroll
    for (int mf = 0; mf < 4; mf++) {
        const int row = m0 + warp_m * 64 + mf * 16 + g_;
#pragma unroll
        for (int nf = 0; nf < 4; nf++) {
            const int col = n0 + warp_n * 32 + nf * 8 + tg * 2;
            const float b0 = bias[col], b1 = bias[col + 1];
            const float v00 = acc[mf][nf][0] + b0, v01 = acc[mf][nf][1] + b1;
            const float v10 = acc[mf][nf][2] + b0, v11 = acc[mf][nf][3] + b1;
            if (mode == 0) {
                *(float2*)(C + (size_t)row * Ncols + col) = make_float2(v00, v01);
                *(float2*)(C + (size_t)(row + 8) * Ncols + col) = make_float2(v10, v11);
            } else {
                const size_t o0 = (size_t)row * Ncols + col;
                const size_t o1 = (size_t)(row + 8) * Ncols + col;
                *(uint32_t*)(Ch + o0) = packbf(v00, v01);
                *(uint32_t*)(Ch + o1) = packbf(v10, v11);
                *(uint32_t*)(Cl + o0) = packbf(v00 - bf2f(v00), v01 - bf2f(v01));
                *(uint32_t*)(Cl + o1) = packbf(v10 - bf2f(v10), v11 - bf2f(v11));
            }
        }
    }
}

// ---------------------------------------------------------------------------
// Flash attention via mma.sync, 3-term bf16 split. Mq=64, Nk=64, hd=128.
// V natural layout + ldmatrix.trans; K/V prefetched intra-tile via cp.async.
// (R7 pipeline: single wait_group 0 at tile top.)
// Writes bf16 hi/lo attn output directly.
// ---------------------------------------------------------------------------
#define FQSTR 272                 // row stride bytes (128 bf16 + 8 pad)
#define FQB   (64 * FQSTR)        // 17408
#define FL_SMEM (6 * FQB)         // 104448

__global__ __launch_bounds__(128) void flash_mma(
    const __nv_bfloat16* __restrict__ qh, const __nv_bfloat16* __restrict__ ql,
    __nv_bfloat16* __restrict__ attnh, __nv_bfloat16* __restrict__ attnl)
{
    extern __shared__ char smem[];
    const uint32_t sb  = smem_u32(smem);
    const uint32_t sQh = sb,            sQl = sb + FQB;
    const uint32_t sKh = sb + 2 * FQB,  sKl = sb + 3 * FQB;
    const uint32_t sVh = sb + 4 * FQB,  sVl = sb + 5 * FQB;

    const int tid = threadIdx.x, wid = tid >> 5, lane = tid & 31;
    const int g = lane >> 2, t = lane & 3;

    int yy = blockIdx.y, b, h, win;
    if (yy < B_ * NFULL) { b = yy / NFULL;  h = yy % NFULL;          win = 0; }
    else { yy -= B_ * NFULL; b = yy / NLOCAL; h = NFULL + yy % NLOCAL; win = 1; }
    const int q0 = blockIdx.x * 64;

    const size_t rb   = (size_t)b * S_ * QKV3 + (size_t)h * HD_;
    const size_t koff = rb + 1536;
    const size_t voff = rb + 3072;

    int kt0 = 0, kt1 = S_ >> 6;
    if (win) {
        kt0 = (q0 >= HWIN) ? ((q0 - HWIN) >> 6) : 0;
        kt1 = min(kt1, ((q0 + 63 + HWIN) >> 6) + 1);
    }

    // Q tiles (once) + first K/V tiles
    for (int u = tid; u < 1024; u += 128) {
        const int r = u >> 4, c = u & 15;
        const size_t go = rb + (size_t)(q0 + r) * QKV3 + c * 8;
        cp16(sQh + r * FQSTR + c * 16, qh + go);
        cp16(sQl + r * FQSTR + c * 16, ql + go);
    }
    {
        const int k0 = kt0 << 6;
        for (int u = tid; u < 1024; u += 128) {
            const int r = u >> 4, c = u & 15;
            const size_t gk = koff + (size_t)(k0 + r) * QKV3 + c * 8;
            const size_t gv = voff + (size_t)(k0 + r) * QKV3 + c * 8;
            cp16(sKh + r * FQSTR + c * 16, qh + gk);
            cp16(sKl + r * FQSTR + c * 16, ql + gk);
            cp16(sVh + r * FQSTR + c * 16, qh + gv);
            cp16(sVl + r * FQSTR + c * 16, ql + gv);
        }
    }
    CP_COMMIT();

    float oacc[16][4];
#pragma unroll
    for (int i = 0; i < 16; i++)
#pragma unroll
        for (int j = 0; j < 4; j++) oacc[i][j] = 0.f;
    float m0 = -1e30f, m1 = -1e30f, l0 = 0.f, l1 = 0.f;

    const int a_row  = wid * 16 + (lane & 15);
    const int a_koff = (lane >> 4) * 16;
    const int b_r    = lane & 7;
    const int b_koff = ((lane >> 3) & 1) * 16;
    const int v_row  = lane & 15;          // trans ldmatrix row (key)
    const int row0   = q0 + wid * 16 + g;

    for (int kt = kt0; kt < kt1; kt++) {
        const int k0 = kt << 6;
        asm volatile("cp.async.wait_group 0;" ::: "memory");
        __syncthreads();

        // S = Q K^T (3-term, pairwise term-major)
        float sacc[8][4];
#pragma unroll
        for (int i = 0; i < 8; i++)
#pragma unroll
            for (int j = 0; j < 4; j++) sacc[i][j] = 0.f;
#pragma unroll
        for (int kc = 0; kc < 8; kc++) {
            uint32_t qah[4], qal[4];
            const uint32_t aoff = a_row * FQSTR + kc * 32 + a_koff;
            ldm_x4(qah, sQh + aoff);
            ldm_x4(qal, sQl + aoff);
#pragma unroll
            for (int np = 0; np < 4; np++) {
                const int n0f = 2 * np, n1f = n0f + 1;
                uint32_t kbh0[2], kbl0[2], kbh1[2], kbl1[2];
                const uint32_t bo0 = (n0f * 8 + b_r) * FQSTR + kc * 32 + b_koff;
                const uint32_t bo1 = (n1f * 8 + b_r) * FQSTR + kc * 32 + b_koff;
                ldm_x2(kbh0, sKh + bo0);
                ldm_x2(kbh1, sKh + bo1);
                ldm_x2(kbl0, sKl + bo0);
                ldm_x2(kbl1, sKl + bo1);
                mma16816(sacc[n0f], qah, kbh0);
                mma16816(sacc[n1f], qah, kbh1);
                mma16816(sacc[n0f], qah, kbl0);
                mma16816(sacc[n1f], qah, kbl1);
                mma16816(sacc[n0f], qal, kbh0);
                mma16816(sacc[n1f], qal, kbh1);
            }
        }
        __syncthreads();   // all warps done reading K smem

        // prefetch next K while softmax+PV run
        if (kt + 1 < kt1) {
            const int kn = (kt + 1) << 6;
            for (int u = tid; u < 1024; u += 128) {
                const int r = u >> 4, c = u & 15;
                const size_t gk = koff + (size_t)(kn + r) * QKV3 + c * 8;
                cp16(sKh + r * FQSTR + c * 16, qh + gk);
                cp16(sKl + r * FQSTR + c * 16, ql + gk);
            }
            CP_COMMIT();
        }

        // scale + mask + online softmax
        float mt0 = -1e30f, mt1 = -1e30f;
#pragma unroll
        for (int nf = 0; nf < 8; nf++) {
#pragma unroll
            for (int e = 0; e < 4; e++) {
                float v = sacc[nf][e] * SCALE;
                if (win) {
                    const int col = k0 + nf * 8 + 2 * t + (e & 1);
                    const int row = row0 + (e >> 1) * 8;
                    const int dq = row - col;
                    if (dq > HWIN || dq < -HWIN) v = -1e30f;
                }
                sacc[nf][e] = v;
            }
            mt0 = fmaxf(mt0, fmaxf(sacc[nf][0], sacc[nf][1]));
            mt1 = fmaxf(mt1, fmaxf(sacc[nf][2], sacc[nf][3]));
        }
        mt0 = fmaxf(mt0, __shfl_xor_sync(0xffffffffu, mt0, 1));
        mt0 = fmaxf(mt0, __shfl_xor_sync(0xffffffffu, mt0, 2));
        mt1 = fmaxf(mt1, __shfl_xor_sync(0xffffffffu, mt1, 1));
        mt1 = fmaxf(mt1, __shfl_xor_sync(0xffffffffu, mt1, 2));
        const float mn0 = fmaxf(m0, mt0), mn1 = fmaxf(m1, mt1);
        const float al0 = __expf(m0 - mn0), al1 = __expf(m1 - mn1);
        m0 = mn0; m1 = mn1;
        l0 *= al0; l1 *= al1;
#pragma unroll
        for (int dn = 0; dn < 16; dn++) {
            oacc[dn][0] *= al0; oacc[dn][1] *= al0;
            oacc[dn][2] *= al1; oacc[dn][3] *= al1;
        }

        // P = exp(S - m), split into bf16 hi/lo A-fragments (register-only)
        uint32_t pah[4][4], pal[4][4];
#pragma unroll
        for (int c = 0; c < 4; c++) {
            float p0 = __expf(sacc[2 * c][0] - mn0);
            float p1 = __expf(sacc[2 * c][1] - mn0);
            float p2 = __expf(sacc[2 * c][2] - mn1);
            float p3 = __expf(sacc[2 * c][3] - mn1);
            float r0 = __expf(sacc[2 * c + 1][0] - mn0);
            float r1 = __expf(sacc[2 * c + 1][1] - mn0);
            float r2 = __expf(sacc[2 * c + 1][2] - mn1);
            float r3 = __expf(sacc[2 * c + 1][3] - mn1);
            l0 += p0 + p1 + r0 + r1;
            l1 += p2 + p3 + r2 + r3;
            pah[c][0] = packbf(p0, p1);
            pah[c][1] = packbf(p2, p3);
            pah[c][2] = packbf(r0, r1);
            pah[c][3] = packbf(r2, r3);
            pal[c][0] = packbf(p0 - bf2f(p0), p1 - bf2f(p1));
            pal[c][1] = packbf(p2 - bf2f(p2), p3 - bf2f(p3));
            pal[c][2] = packbf(r0 - bf2f(r0), r1 - bf2f(r1));
            pal[c][3] = packbf(r2 - bf2f(r2), r3 - bf2f(r3));
        }

        // O += P @ V (3-term, pairwise term-major); V natural, trans ldmatrix
#pragma unroll
        for (int c = 0; c < 4; c++) {
#pragma unroll
            for (int dp = 0; dp < 8; dp++) {
                const int d0 = 2 * dp, d1 = d0 + 1;
                uint32_t vbh0[2], vbl0[2], vbh1[2], vbl1[2];
                const uint32_t vo0 = (c * 16 + v_row) * FQSTR + d0 * 16;
                const uint32_t vo1 = (c * 16 + v_row) * FQSTR + d1 * 16;
                ldm_x2t(vbh0, sVh + vo0);
                ldm_x2t(vbh1, sVh + vo1);
                ldm_x2t(vbl0, sVl + vo0);
                ldm_x2t(vbl1, sVl + vo1);
                mma16816(oacc[d0], pah[c], vbh0);
                mma16816(oacc[d1], pah[c], vbh1);
                mma16816(oacc[d0], pah[c], vbl0);
                mma16816(oacc[d1], pah[c], vbl1);
                mma16816(oacc[d0], pal[c], vbh0);
                mma16816(oacc[d1], pal[c], vbh1);
            }
        }
        __syncthreads();   // all warps done reading V smem

        if (kt + 1 < kt1) {
            const int kn = (kt + 1) << 6;
            for (int u = tid; u < 1024; u += 128) {
                const int r = u >> 4, c = u & 15;
                const size_t gv = voff + (size_t)(kn + r) * QKV3 + c * 8;
                cp16(sVh + r * FQSTR + c * 16, qh + gv);
                cp16(sVl + r * FQSTR + c * 16, ql + gv);
            }
            CP_COMMIT();
        }
    }

    // finalize: reduce l across t-group, normalize, write bf16 hi/lo
    l0 += __shfl_xor_sync(0xffffffffu, l0, 1);
    l0 += __shfl_xor_sync(0xffffffffu, l0, 2);
    l1 += __shfl_xor_sync(0xffffffffu, l1, 1);
    l1 += __shfl_xor_sync(0xffffffffu, l1, 2);
    const float inv0 = 1.f / l0, inv1 = 1.f / l1;

    const size_t ob0 = ((size_t)b * S_ + row0) * D_ + h * HD_;
    const size_t ob1 = ob0 + 8 * D_;
#pragma unroll
    for (int dn = 0; dn < 16; dn++) {
        const int col = dn * 8 + 2 * t;
        const float v00 = oacc[dn][0] * inv0, v01 = oacc[dn][1] * inv0;
        const float v10 = oacc[dn][2] * inv1, v11 = oacc[dn][3] * inv1;
        *(uint32_t*)(attnh + ob0 + col) = packbf(v00, v01);
        *(uint32_t*)(attnh + ob1 + col) = packbf(v10, v11);
        *(uint32_t*)(attnl + ob0 + col) = packbf(v00 - bf2f(v00), v01 - bf2f(v01));
        *(uint32_t*)(attnl + ob1 + col) = packbf(v10 - bf2f(v10), v11 - bf2f(v11));
    }
}

// ---------------------------------------------------------------------------
// Global heads: qkv reconstructed from bf16 hi+lo; writes bf16 hi/lo attn.
// ---------------------------------------------------------------------------
__global__ __launch_bounds__(256) void global_attn(
    const __nv_bfloat16* __restrict__ qh, const __nv_bfloat16* __restrict__ ql,
    __nv_bfloat16* __restrict__ attnh, __nv_bfloat16* __restrict__ attnl)
{
    const int wip  = threadIdx.x >> 5;
    const int lane = threadIdx.x & 31;
    const int wid  = blockIdx.x * 8 + wip;
    const int q  = wid & (S_ - 1);
    const int hg = (wid >> 11) & 1;
    const int b  = wid >> 12;
    const int h  = NFULL + NLOCAL + hg;

    const size_t base = (size_t)b * S_ * QKV3 + (size_t)h * HD_;
    const size_t qp  = base + (size_t)q * QKV3;
    const size_t kp0 = base + 1536;
    const size_t kp1 = base + 1536 + (size_t)(S_ - 1) * QKV3;
    const size_t vp0 = base + 3072;
    const size_t vp1 = base + 3072 + (size_t)(S_ - 1) * QKV3;

#define RD(off, d) (__bfloat162float(qh[(off) + (d)]) + __bfloat162float(ql[(off) + (d)]))

    float s0 = 0.f, s1 = 0.f;
#pragma unroll
    for (int c = 0; c < 4; c++) {
        const int d = lane + (c << 5);
        const float qd = RD(qp, d);
        s0 += qd * RD(kp0, d);
        s1 += qd * RD(kp1, d);
    }
#pragma unroll
    for (int o = 16; o > 0; o >>= 1) {
        s0 += __shfl_xor_sync(0xffffffffu, s0, o);
        s1 += __shfl_xor_sync(0xffffffffu, s1, o);
    }
    s0 *= SCALE; s1 *= SCALE;
    const float mx = fmaxf(s0, s1);
    float e0 = __expf(s0 - mx), e1 = __expf(s1 - mx);
    const float inv = 1.f / (e0 + e1);
    e0 *= inv; e1 *= inv;

    const size_t op = ((size_t)b * S_ + q) * D_ + h * HD_;
#pragma unroll
    for (int c = 0; c < 4; c++) {
        const int d = lane + (c << 5);
        const float o = e0 * RD(vp0, d) + e1 * RD(vp1, d);
        const __nv_bfloat16 oh = __float2bfloat16(o);
        attnh[op + d] = oh;
        attnl[op + d] = __float2bfloat16(o - __bfloat162float(oh));
    }
#undef RD
}

// ---------------------------------------------------------------------------
extern "C" void kernel_launch(void* const* d_in, const int* in_sizes, int n_in,
                              void* d_out, int out_size)
{
    const float* x    = (const float*)d_in[0];
    const float* Wqkv = (const float*)d_in[1];
    const float* bqkv = (const float*)d_in[2];
    const float* Wout = (const float*)d_in[3];
    const float* bout = (const float*)d_in[4];
    float* out = (float*)d_out;

    __nv_bfloat16 *qkvh, *qkvl, *Xh, *Xl, *A2h, *A2l, *Wqh, *Wql, *Woh, *Wol;
    cudaGetSymbolAddress((void**)&qkvh, g_qkvh);
    cudaGetSymbolAddress((void**)&qkvl, g_qkvl);
    cudaGetSymbolAddress((void**)&Xh,  g_Xh);
    cudaGetSymbolAddress((void**)&Xl,  g_Xl);
    cudaGetSymbolAddress((void**)&A2h, g_A2h);
    cudaGetSymbolAddress((void**)&A2l, g_A2l);
    cudaGetSymbolAddress((void**)&Wqh, g_Wqh);
    cudaGetSymbolAddress((void**)&Wql, g_Wql);
    cudaGetSymbolAddress((void**)&Woh, g_Woh);
    cudaGetSymbolAddress((void**)&Wol, g_Wol);

    cudaFuncSetAttribute(gemm3t,
                         cudaFuncAttributeMaxDynamicSharedMemorySize, GEMM_SMEM);
    cudaFuncSetAttribute(flash_mma,
                         cudaFuncAttributeMaxDynamicSharedMemorySize, FL_SMEM);

    // Input/weight splits
    k_split<<<(MROWS * KDIM) / 1024, 256>>>(x, Xh, Xl, MROWS * KDIM);
    k_splitT<<<dim3(QKV3 / 32, KDIM / 32), 256>>>(Wqkv, Wqh, Wql, KDIM, QKV3);
    k_splitT<<<dim3(D_ / 32, KDIM / 32), 256>>>(Wout, Woh, Wol, KDIM, D_);

    // 1) QKV projection -> bf16 hi/lo; 4 dead global-head K/V tiles skipped
    gemm3t<<<dim3(32, MROWS / 128), 256, GEMM_SMEM>>>(
        Xh, Xl, Wqh, Wql, bqkv, nullptr, qkvh, qkvl, QKV3, 1);
    // exact fixup for the skipped columns at the 4 rows global_attn reads
    fix_globalqkv<<<16, 128>>>(x, Wqkv, bqkv, qkvh, qkvl);

    // 2) Attention (full + windowed fused) + global heads -> bf16 hi/lo attn
    flash_mma<<<dim3(S_ / 64, B_ * (NFULL + NLOCAL)), 128, FL_SMEM>>>(
        qkvh, qkvl, A2h, A2l);
    global_attn<<<(B_ * 2 * S_) / 8, 256>>>(qkvh, qkvl, A2h, A2l);

    // 3) Output projection -> fp32 final
    gemm3t<<<dim3(D_ / 128, MROWS / 128), 256, GEMM_SMEM>>>(
        A2h, A2l, Woh, Wol, bout, out, nullptr, nullptr, D_, 0);
}

// round 13
// speedup vs baseline: 1.1759x; 1.1759x over previous
#include <cuda_runtime.h>
#include <cuda_bf16.h>
#include <cuda_fp16.h>
#include <stdint.h>
#include <math.h>

#define B_    2
#define S_    2048
#define D_    1536
#define QKV3  4608
#define HD_   128
#define NFULL 6
#define NLOCAL 4
#define HWIN  32
#define SCALE 0.08838834764831845f   // 1/sqrt(128)
#define KDIM  1536
#define MROWS 4096                   // B_*S_

// ---------------------------------------------------------------------------
// Scratch (device globals: allocation-free)
// ---------------------------------------------------------------------------
__device__ __nv_bfloat16 g_qkvh[(size_t)MROWS * QKV3];   // flash input (bf16 3-term)
__device__ __nv_bfloat16 g_qkvl[(size_t)MROWS * QKV3];
__device__ __half g_Xh[(size_t)MROWS * KDIM];            // fp16 2-term A for QKV gemm
__device__ __half g_Xl[(size_t)MROWS * KDIM];
__device__ __half g_A2h[(size_t)MROWS * KDIM];           // attn out, fp16 2-term
__device__ __half g_A2l[(size_t)MROWS * KDIM];
__device__ __half g_Wq[(size_t)QKV3 * KDIM];             // weights, fp16 1-term [N][K]
__device__ __half g_Wo[(size_t)D_ * KDIM];

// ---------------------------------------------------------------------------
// PTX helpers (sm_80-baseline: legal on plain compute_103 target)
// ---------------------------------------------------------------------------
__device__ __forceinline__ uint32_t smem_u32(const void* p) {
    uint32_t a;
    asm("{ .reg .u64 t; cvta.to.shared.u64 t, %1; cvt.u32.u64 %0, t; }"
        : "=r"(a) : "l"(p));
    return a;
}
__device__ __forceinline__ void cp16(uint32_t d, const void* s) {
    asm volatile("cp.async.cg.shared.global [%0], [%1], 16;" :: "r"(d), "l"(s));
}
#define CP_COMMIT() asm volatile("cp.async.commit_group;" ::: "memory")

__device__ __forceinline__ void ldm_x4(uint32_t* r, uint32_t addr) {
    asm volatile("ldmatrix.sync.aligned.m8n8.x4.shared.b16 {%0,%1,%2,%3}, [%4];"
                 : "=r"(r[0]), "=r"(r[1]), "=r"(r[2]), "=r"(r[3]) : "r"(addr));
}
__device__ __forceinline__ void ldm_x2(uint32_t* r, uint32_t addr) {
    asm volatile("ldmatrix.sync.aligned.m8n8.x2.shared.b16 {%0,%1}, [%2];"
                 : "=r"(r[0]), "=r"(r[1]) : "r"(addr));
}
__device__ __forceinline__ void ldm_x2t(uint32_t* r, uint32_t addr) {
    asm volatile("ldmatrix.sync.aligned.m8n8.x2.trans.shared.b16 {%0,%1}, [%2];"
                 : "=r"(r[0]), "=r"(r[1]) : "r"(addr));
}
// bf16 mma (flash)
__device__ __forceinline__ void mma16816(float* c, const uint32_t* a,
                                         const uint32_t* b) {
    asm volatile(
        "mma.sync.aligned.m16n8k16.row.col.f32.bf16.bf16.f32 "
        "{%0,%1,%2,%3}, {%4,%5,%6,%7}, {%8,%9}, {%0,%1,%2,%3};"
        : "+f"(c[0]), "+f"(c[1]), "+f"(c[2]), "+f"(c[3])
        : "r"(a[0]), "r"(a[1]), "r"(a[2]), "r"(a[3]), "r"(b[0]), "r"(b[1]));
}
// fp16 mma (dense gemms)
__device__ __forceinline__ void mma16816h(float* c, const uint32_t* a,
                                          const uint32_t* b) {
    asm volatile(
        "mma.sync.aligned.m16n8k16.row.col.f32.f16.f16.f32 "
        "{%0,%1,%2,%3}, {%4,%5,%6,%7}, {%8,%9}, {%0,%1,%2,%3};"
        : "+f"(c[0]), "+f"(c[1]), "+f"(c[2]), "+f"(c[3])
        : "r"(a[0]), "r"(a[1]), "r"(a[2]), "r"(a[3]), "r"(b[0]), "r"(b[1]));
}
// pack two f32 -> bf16x2 / f16x2 (first arg -> low half / lower address)
__device__ __forceinline__ uint32_t packbf(float lo, float hi) {
    uint32_t r;
    asm("cvt.rn.bf16x2.f32 %0, %1, %2;" : "=r"(r) : "f"(hi), "f"(lo));
    return r;
}
__device__ __forceinline__ uint32_t packh(float lo, float hi) {
    uint32_t r;
    asm("cvt.rn.f16x2.f32 %0, %1, %2;" : "=r"(r) : "f"(hi), "f"(lo));
    return r;
}
__device__ __forceinline__ float bf2f(float p) {
    return __bfloat162float(__float2bfloat16(p));
}
__device__ __forceinline__ float h2f(float p) {
    return __half2float(__float2half(p));
}

// ---------------------------------------------------------------------------
// Split kernels
// ---------------------------------------------------------------------------
// fp32 -> fp16 (hi, lo) 2-term
__global__ __launch_bounds__(256) void k_split_h2(
    const float* __restrict__ in, __half* __restrict__ hi,
    __half* __restrict__ lo, int n)
{
    int i = (blockIdx.x * 256 + threadIdx.x) * 4;
    if (i >= n) return;
    float4 v = *(const float4*)(in + i);
    uint32_t* hp = (uint32_t*)(hi + i);
    uint32_t* lp = (uint32_t*)(lo + i);
    hp[0] = packh(v.x, v.y);
    hp[1] = packh(v.z, v.w);
    lp[0] = packh(v.x - h2f(v.x), v.y - h2f(v.y));
    lp[1] = packh(v.z - h2f(v.z), v.w - h2f(v.w));
}

// fp32 [K,N] -> fp16 [N,K] single-term transposed
__global__ __launch_bounds__(256) void k_splitT_h1(
    const float* __restrict__ in, __half* __restrict__ hi, int Kd, int Nd)
{
    __shared__ float t[32][33];
    const int n0 = blockIdx.x * 32, k0 = blockIdx.y * 32;
    const int tx = threadIdx.x & 31, ty = threadIdx.x >> 5;
#pragma unroll
    for (int j = 0; j < 32; j += 8)
        t[ty + j][tx] = in[(size_t)(k0 + ty + j) * Nd + n0 + tx];
    __syncthreads();
#pragma unroll
    for (int j = 0; j < 32; j += 8)
        hi[(size_t)(n0 + ty + j) * Kd + k0 + tx] = __float2half(t[tx][ty + j]);
}

// ---------------------------------------------------------------------------
// Fixup: exact fp32 dot products for the 4 skipped global-head K/V column
// tiles at the only 4 rows global_attn reads.
// ---------------------------------------------------------------------------
__global__ __launch_bounds__(128) void fix_globalqkv(
    const float* __restrict__ x, const float* __restrict__ Wqkv,
    const float* __restrict__ bqkv,
    __nv_bfloat16* __restrict__ qkvh, __nv_bfloat16* __restrict__ qkvl)
{
    __shared__ float xs[KDIM];
    const int rows[4] = {0, S_ - 1, S_, 2 * S_ - 1};
    const int cols[4] = {2816, 2944, 4352, 4480};
    const int row = rows[blockIdx.x >> 2];
    const int c   = cols[blockIdx.x & 3] + threadIdx.x;

    for (int k = threadIdx.x; k < KDIM; k += 128)
        xs[k] = x[(size_t)row * KDIM + k];
    __syncthreads();

    float s = 0.f;
#pragma unroll 8
    for (int k = 0; k < KDIM; k++)
        s += xs[k] * Wqkv[(size_t)k * QKV3 + c];
    s += bqkv[c];

    const size_t o = (size_t)row * QKV3 + c;
    const __nv_bfloat16 h = __float2bfloat16(s);
    qkvh[o] = h;
    qkvl[o] = __float2bfloat16(s - __bfloat162float(h));
}

// ---------------------------------------------------------------------------
// FP16 2-term GEMM: acc = Ah@B^T + Al@B^T + bias.
// A: [M][K] fp16 hi/lo. B: [N][K] fp16. 128x128 tile, BK=32, 8 warps (2x4),
// 2-stage cp.async, 2 CTAs/SM. Smem/stage = 3 tiles x 10240 = 30720.
// mode 0: write fp32 C. mode 1: write bf16 hi/lo (Ch, Cl) and remap
// blockIdx.x to skip the 4 dead global-head column tiles {22,23,34,35}.
// ---------------------------------------------------------------------------
#define NCH    (KDIM / 32)          // 48
#define AROWB  80
#define TILEB  (128 * AROWB)        // 10240
#define STAGE2 (3 * TILEB)          // 30720
#define GEMM2_SMEM (2 * STAGE2)     // 61440

__global__ __launch_bounds__(256, 2) void gemm2h(
    const __half* __restrict__ Ahg, const __half* __restrict__ Alg,
    const __half* __restrict__ Bg,
    const float* __restrict__ bias, float* __restrict__ C,
    __nv_bfloat16* __restrict__ Ch, __nv_bfloat16* __restrict__ Cl,
    int Ncols, int mode)
{
    extern __shared__ char smem[];
    const uint32_t sb = smem_u32(smem);
    const int tid  = threadIdx.x;
    const int wid  = tid >> 5;
    const int lane = tid & 31;
    const int warp_m = wid & 1;
    const int warp_n = wid >> 1;
    const int m0 = blockIdx.y * 128;
    int bx = blockIdx.x;
    if (mode == 1 && bx >= 22) bx += 2;   // skip dead tiles 22,23 (34,35 off-grid)
    const int n0 = bx * 128;

    const char* gAh = (const char*)(Ahg + (size_t)m0 * KDIM);
    const char* gAl = (const char*)(Alg + (size_t)m0 * KDIM);
    const char* gB  = (const char*)(Bg  + (size_t)n0 * KDIM);

    float acc[4][4][4];
#pragma unroll
    for (int i = 0; i < 4; i++)
#pragma unroll
        for (int j = 0; j < 4; j++)
#pragma unroll
            for (int k = 0; k < 4; k++) acc[i][j][k] = 0.f;

    // 1536 16B-units per chunk (3 tiles x 128 rows x 4 segs) / 256 thr = 6
#define LOAD_CHUNK2(ch, stage) do {                                            \
        const uint32_t st = sb + (stage) * STAGE2;                             \
        const size_t kb = (size_t)(ch) * 64;                                   \
        _Pragma("unroll")                                                      \
        for (int t = 0; t < 6; t++) {                                          \
            const int u = tid + t * 256;                                       \
            const int tile = u >> 9;                                           \
            const int r = (u >> 2) & 127;                                      \
            const int c = u & 3;                                               \
            const char* g = (tile == 0) ? gAh : (tile == 1) ? gAl : gB;        \
            cp16(st + tile * TILEB + r * AROWB + c * 16,                       \
                 g + (size_t)r * (KDIM * 2) + kb + c * 16);                    \
        }                                                                      \
        CP_COMMIT();                                                           \
    } while (0)

    LOAD_CHUNK2(0, 0);
    LOAD_CHUNK2(1, 1);

    const int a_row  = warp_m * 64 + (lane & 15);
    const int a_koff = (lane >> 4) * 16;
    const int b_row  = warp_n * 32 + (lane & 7);
    const int b_koff = ((lane >> 3) & 1) * 16;

    for (int i = 0; i < NCH; i++) {
        const int p = i & 1;
        if (i + 1 < NCH) asm volatile("cp.async.wait_group 1;" ::: "memory");
        else             asm volatile("cp.async.wait_group 0;" ::: "memory");
        __syncthreads();

        const uint32_t sAh = sb + p * STAGE2;
        const uint32_t sAl = sAh + TILEB;
        const uint32_t sBh = sAh + 2 * TILEB;

#pragma unroll
        for (int kk = 0; kk < 2; kk++) {
            uint32_t bh[4][2];
#pragma unroll
            for (int nf = 0; nf < 4; nf++) {
                const uint32_t off = (b_row + nf * 8) * AROWB + kk * 32 + b_koff;
                ldm_x2(bh[nf], sBh + off);
            }
#pragma unroll
            for (int mf = 0; mf < 4; mf++) {
                uint32_t ah[4], al[4];
                const uint32_t off = (a_row + mf * 16) * AROWB + kk * 32 + a_koff;
                ldm_x4(ah, sAh + off);
                ldm_x4(al, sAl + off);
#pragma unroll
                for (int nf = 0; nf < 4; nf++) mma16816h(acc[mf][nf], ah, bh[nf]);
#pragma unroll
                for (int nf = 0; nf < 4; nf++) mma16816h(acc[mf][nf], al, bh[nf]);
            }
        }
        __syncthreads();
        if (i + 2 < NCH) LOAD_CHUNK2(i + 2, p);
        else CP_COMMIT();
    }

    const int g_  = lane >> 2;
    const int tg  = lane & 3;
#pragma unroll
    for (int mf = 0; mf < 4; mf++) {
        const int row = m0 + warp_m * 64 + mf * 16 + g_;
#pragma unroll
        for (int nf = 0; nf < 4; nf++) {
            const int col = n0 + warp_n * 32 + nf * 8 + tg * 2;
            const float b0 = bias[col], b1 = bias[col + 1];
            const float v00 = acc[mf][nf][0] + b0, v01 = acc[mf][nf][1] + b1;
            const float v10 = acc[mf][nf][2] + b0, v11 = acc[mf][nf][3] + b1;
            if (mode == 0) {
                *(float2*)(C + (size_t)row * Ncols + col) = make_float2(v00, v01);
                *(float2*)(C + (size_t)(row + 8) * Ncols + col) = make_float2(v10, v11);
            } else {
                const size_t o0 = (size_t)row * Ncols + col;
                const size_t o1 = (size_t)(row + 8) * Ncols + col;
                *(uint32_t*)(Ch + o0) = packbf(v00, v01);
                *(uint32_t*)(Ch + o1) = packbf(v10, v11);
                *(uint32_t*)(Cl + o0) = packbf(v00 - bf2f(v00), v01 - bf2f(v01));
                *(uint32_t*)(Cl + o1) = packbf(v10 - bf2f(v10), v11 - bf2f(v11));
            }
        }
    }
}

// ---------------------------------------------------------------------------
// Flash attention via mma.sync, 3-term bf16 split. Mq=64, Nk=64, hd=128.
// V natural layout + ldmatrix.trans; K/V prefetched intra-tile via cp.async.
// Writes fp16 hi/lo attn output (input to the fp16 out-projection).
// ---------------------------------------------------------------------------
#define FQSTR 272                 // row stride bytes (128 bf16 + 8 pad)
#define FQB   (64 * FQSTR)        // 17408
#define FL_SMEM (6 * FQB)         // 104448

__global__ __launch_bounds__(128) void flash_mma(
    const __nv_bfloat16* __restrict__ qh, const __nv_bfloat16* __restrict__ ql,
    __half* __restrict__ attnh, __half* __restrict__ attnl)
{
    extern __shared__ char smem[];
    const uint32_t sb  = smem_u32(smem);
    const uint32_t sQh = sb,            sQl = sb + FQB;
    const uint32_t sKh = sb + 2 * FQB,  sKl = sb + 3 * FQB;
    const uint32_t sVh = sb + 4 * FQB,  sVl = sb + 5 * FQB;

    const int tid = threadIdx.x, wid = tid >> 5, lane = tid & 31;
    const int g = lane >> 2, t = lane & 3;

    int yy = blockIdx.y, b, h, win;
    if (yy < B_ * NFULL) { b = yy / NFULL;  h = yy % NFULL;          win = 0; }
    else { yy -= B_ * NFULL; b = yy / NLOCAL; h = NFULL + yy % NLOCAL; win = 1; }
    const int q0 = blockIdx.x * 64;

    const size_t rb   = (size_t)b * S_ * QKV3 + (size_t)h * HD_;
    const size_t koff = rb + 1536;
    const size_t voff = rb + 3072;

    int kt0 = 0, kt1 = S_ >> 6;
    if (win) {
        kt0 = (q0 >= HWIN) ? ((q0 - HWIN) >> 6) : 0;
        kt1 = min(kt1, ((q0 + 63 + HWIN) >> 6) + 1);
    }

    // Q tiles (once) + first K/V tiles
    for (int u = tid; u < 1024; u += 128) {
        const int r = u >> 4, c = u & 15;
        const size_t go = rb + (size_t)(q0 + r) * QKV3 + c * 8;
        cp16(sQh + r * FQSTR + c * 16, qh + go);
        cp16(sQl + r * FQSTR + c * 16, ql + go);
    }
    {
        const int k0 = kt0 << 6;
        for (int u = tid; u < 1024; u += 128) {
            const int r = u >> 4, c = u & 15;
            const size_t gk = koff + (size_t)(k0 + r) * QKV3 + c * 8;
            const size_t gv = voff + (size_t)(k0 + r) * QKV3 + c * 8;
            cp16(sKh + r * FQSTR + c * 16, qh + gk);
            cp16(sKl + r * FQSTR + c * 16, ql + gk);
            cp16(sVh + r * FQSTR + c * 16, qh + gv);
            cp16(sVl + r * FQSTR + c * 16, ql + gv);
        }
    }
    CP_COMMIT();

    float oacc[16][4];
#pragma unroll
    for (int i = 0; i < 16; i++)
#pragma unroll
        for (int j = 0; j < 4; j++) oacc[i][j] = 0.f;
    float m0 = -1e30f, m1 = -1e30f, l0 = 0.f, l1 = 0.f;

    const int a_row  = wid * 16 + (lane & 15);
    const int a_koff = (lane >> 4) * 16;
    const int b_r    = lane & 7;
    const int b_koff = ((lane >> 3) & 1) * 16;
    const int v_row  = lane & 15;          // trans ldmatrix row (key)
    const int row0   = q0 + wid * 16 + g;

    for (int kt = kt0; kt < kt1; kt++) {
        const int k0 = kt << 6;
        asm volatile("cp.async.wait_group 0;" ::: "memory");
        __syncthreads();

        // S = Q K^T (3-term, pairwise term-major)
        float sacc[8][4];
#pragma unroll
        for (int i = 0; i < 8; i++)
#pragma unroll
            for (int j = 0; j < 4; j++) sacc[i][j] = 0.f;
#pragma unroll
        for (int kc = 0; kc < 8; kc++) {
            uint32_t qah[4], qal[4];
            const uint32_t aoff = a_row * FQSTR + kc * 32 + a_koff;
            ldm_x4(qah, sQh + aoff);
            ldm_x4(qal, sQl + aoff);
#pragma unroll
            for (int np = 0; np < 4; np++) {
                const int n0f = 2 * np, n1f = n0f + 1;
                uint32_t kbh0[2], kbl0[2], kbh1[2], kbl1[2];
                const uint32_t bo0 = (n0f * 8 + b_r) * FQSTR + kc * 32 + b_koff;
                const uint32_t bo1 = (n1f * 8 + b_r) * FQSTR + kc * 32 + b_koff;
                ldm_x2(kbh0, sKh + bo0);
                ldm_x2(kbh1, sKh + bo1);
                ldm_x2(kbl0, sKl + bo0);
                ldm_x2(kbl1, sKl + bo1);
                mma16816(sacc[n0f], qah, kbh0);
                mma16816(sacc[n1f], qah, kbh1);
                mma16816(sacc[n0f], qah, kbl0);
                mma16816(sacc[n1f], qah, kbl1);
                mma16816(sacc[n0f], qal, kbh0);
                mma16816(sacc[n1f], qal, kbh1);
            }
        }
        __syncthreads();   // all warps done reading K smem

        // prefetch next K while softmax+PV run
        if (kt + 1 < kt1) {
            const int kn = (kt + 1) << 6;
            for (int u = tid; u < 1024; u += 128) {
                const int r = u >> 4, c = u & 15;
                const size_t gk = koff + (size_t)(kn + r) * QKV3 + c * 8;
                cp16(sKh + r * FQSTR + c * 16, qh + gk);
                cp16(sKl + r * FQSTR + c * 16, ql + gk);
            }
            CP_COMMIT();
        }

        // scale + mask + online softmax
        float mt0 = -1e30f, mt1 = -1e30f;
#pragma unroll
        for (int nf = 0; nf < 8; nf++) {
#pragma unroll
            for (int e = 0; e < 4; e++) {
                float v = sacc[nf][e] * SCALE;
                if (win) {
                    const int col = k0 + nf * 8 + 2 * t + (e & 1);
                    const int row = row0 + (e >> 1) * 8;
                    const int dq = row - col;
                    if (dq > HWIN || dq < -HWIN) v = -1e30f;
                }
                sacc[nf][e] = v;
            }
            mt0 = fmaxf(mt0, fmaxf(sacc[nf][0], sacc[nf][1]));
            mt1 = fmaxf(mt1, fmaxf(sacc[nf][2], sacc[nf][3]));
        }
        mt0 = fmaxf(mt0, __shfl_xor_sync(0xffffffffu, mt0, 1));
        mt0 = fmaxf(mt0, __shfl_xor_sync(0xffffffffu, mt0, 2));
        mt1 = fmaxf(mt1, __shfl_xor_sync(0xffffffffu, mt1, 1));
        mt1 = fmaxf(mt1, __shfl_xor_sync(0xffffffffu, mt1, 2));
        const float mn0 = fmaxf(m0, mt0), mn1 = fmaxf(m1, mt1);
        const float al0 = __expf(m0 - mn0), al1 = __expf(m1 - mn1);
        m0 = mn0; m1 = mn1;
        l0 *= al0; l1 *= al1;
#pragma unroll
        for (int dn = 0; dn < 16; dn++) {
            oacc[dn][0] *= al0; oacc[dn][1] *= al0;
            oacc[dn][2] *= al1; oacc[dn][3] *= al1;
        }

        // P = exp(S - m), split into bf16 hi/lo A-fragments (register-only)
        uint32_t pah[4][4], pal[4][4];
#pragma unroll
        for (int c = 0; c < 4; c++) {
            float p0 = __expf(sacc[2 * c][0] - mn0);
            float p1 = __expf(sacc[2 * c][1] - mn0);
            float p2 = __expf(sacc[2 * c][2] - mn1);
            float p3 = __expf(sacc[2 * c][3] - mn1);
            float r0 = __expf(sacc[2 * c + 1][0] - mn0);
            float r1 = __expf(sacc[2 * c + 1][1] - mn0);
            float r2 = __expf(sacc[2 * c + 1][2] - mn1);
            float r3 = __expf(sacc[2 * c + 1][3] - mn1);
            l0 += p0 + p1 + r0 + r1;
            l1 += p2 + p3 + r2 + r3;
            pah[c][0] = packbf(p0, p1);
            pah[c][1] = packbf(p2, p3);
            pah[c][2] = packbf(r0, r1);
            pah[c][3] = packbf(r2, r3);
            pal[c][0] = packbf(p0 - bf2f(p0), p1 - bf2f(p1));
            pal[c][1] = packbf(p2 - bf2f(p2), p3 - bf2f(p3));
            pal[c][2] = packbf(r0 - bf2f(r0), r1 - bf2f(r1));
            pal[c][3] = packbf(r2 - bf2f(r2), r3 - bf2f(r3));
        }

        // O += P @ V (3-term, pairwise term-major); V natural, trans ldmatrix
#pragma unroll
        for (int c = 0; c < 4; c++) {
#pragma unroll
            for (int dp = 0; dp < 8; dp++) {
                const int d0 = 2 * dp, d1 = d0 + 1;
                uint32_t vbh0[2], vbl0[2], vbh1[2], vbl1[2];
                const uint32_t vo0 = (c * 16 + v_row) * FQSTR + d0 * 16;
                const uint32_t vo1 = (c * 16 + v_row) * FQSTR + d1 * 16;
                ldm_x2t(vbh0, sVh + vo0);
                ldm_x2t(vbh1, sVh + vo1);
                ldm_x2t(vbl0, sVl + vo0);
                ldm_x2t(vbl1, sVl + vo1);
                mma16816(oacc[d0], pah[c], vbh0);
                mma16816(oacc[d1], pah[c], vbh1);
                mma16816(oacc[d0], pah[c], vbl0);
                mma16816(oacc[d1], pah[c], vbl1);
                mma16816(oacc[d0], pal[c], vbh0);
                mma16816(oacc[d1], pal[c], vbh1);
            }
        }
        __syncthreads();   // all warps done reading V smem

        if (kt + 1 < kt1) {
            const int kn = (kt + 1) << 6;
            for (int u = tid; u < 1024; u += 128) {
                const int r = u >> 4, c = u & 15;
                const size_t gv = voff + (size_t)(kn + r) * QKV3 + c * 8;
                cp16(sVh + r * FQSTR + c * 16, qh + gv);
                cp16(sVl + r * FQSTR + c * 16, ql + gv);
            }
            CP_COMMIT();
        }
    }

    // finalize: reduce l across t-group, normalize, write fp16 hi/lo
    l0 += __shfl_xor_sync(0xffffffffu, l0, 1);
    l0 += __shfl_xor_sync(0xffffffffu, l0, 2);
    l1 += __shfl_xor_sync(0xffffffffu, l1, 1);
    l1 += __shfl_xor_sync(0xffffffffu, l1, 2);
    const float inv0 = 1.f / l0, inv1 = 1.f / l1;

    const size_t ob0 = ((size_t)b * S_ + row0) * D_ + h * HD_;
    const size_t ob1 = ob0 + 8 * D_;
#pragma unroll
    for (int dn = 0; dn < 16; dn++) {
        const int col = dn * 8 + 2 * t;
        const float v00 = oacc[dn][0] * inv0, v01 = oacc[dn][1] * inv0;
        const float v10 = oacc[dn][2] * inv1, v11 = oacc[dn][3] * inv1;
        *(uint32_t*)(attnh + ob0 + col) = packh(v00, v01);
        *(uint32_t*)(attnh + ob1 + col) = packh(v10, v11);
        *(uint32_t*)(attnl + ob0 + col) = packh(v00 - h2f(v00), v01 - h2f(v01));
        *(uint32_t*)(attnl + ob1 + col) = packh(v10 - h2f(v10), v11 - h2f(v11));
    }
}

// ---------------------------------------------------------------------------
// Global heads: qkv reconstructed from bf16 hi+lo; writes fp16 hi/lo attn.
// ---------------------------------------------------------------------------
__global__ __launch_bounds__(256) void global_attn(
    const __nv_bfloat16* __restrict__ qh, const __nv_bfloat16* __restrict__ ql,
    __half* __restrict__ attnh, __half* __restrict__ attnl)
{
    const int wip  = threadIdx.x >> 5;
    const int lane = threadIdx.x & 31;
    const int wid  = blockIdx.x * 8 + wip;
    const int q  = wid & (S_ - 1);
    const int hg = (wid >> 11) & 1;
    const int b  = wid >> 12;
    const int h  = NFULL + NLOCAL + hg;

    const size_t base = (size_t)b * S_ * QKV3 + (size_t)h * HD_;
    const size_t qp  = base + (size_t)q * QKV3;
    const size_t kp0 = base + 1536;
    const size_t kp1 = base + 1536 + (size_t)(S_ - 1) * QKV3;
    const size_t vp0 = base + 3072;
    const size_t vp1 = base + 3072 + (size_t)(S_ - 1) * QKV3;

#define RD(off, d) (__bfloat162float(qh[(off) + (d)]) + __bfloat162float(ql[(off) + (d)]))

    float s0 = 0.f, s1 = 0.f;
#pragma unroll
    for (int c = 0; c < 4; c++) {
        const int d = lane + (c << 5);
        const float qd = RD(qp, d);
        s0 += qd * RD(kp0, d);
        s1 += qd * RD(kp1, d);
    }
#pragma unroll
    for (int o = 16; o > 0; o >>= 1) {
        s0 += __shfl_xor_sync(0xffffffffu, s0, o);
        s1 += __shfl_xor_sync(0xffffffffu, s1, o);
    }
    s0 *= SCALE; s1 *= SCALE;
    const float mx = fmaxf(s0, s1);
    float e0 = __expf(s0 - mx), e1 = __expf(s1 - mx);
    const float inv = 1.f / (e0 + e1);
    e0 *= inv; e1 *= inv;

    const size_t op = ((size_t)b * S_ + q) * D_ + h * HD_;
#pragma unroll
    for (int c = 0; c < 4; c++) {
        const int d = lane + (c << 5);
        const float o = e0 * RD(vp0, d) + e1 * RD(vp1, d);
        const __half oh = __float2half(o);
        attnh[op + d] = oh;
        attnl[op + d] = __float2half(o - __half2float(oh));
    }
#undef RD
}

// ---------------------------------------------------------------------------
extern "C" void kernel_launch(void* const* d_in, const int* in_sizes, int n_in,
                              void* d_out, int out_size)
{
    const float* x    = (const float*)d_in[0];
    const float* Wqkv = (const float*)d_in[1];
    const float* bqkv = (const float*)d_in[2];
    const float* Wout = (const float*)d_in[3];
    const float* bout = (const float*)d_in[4];
    float* out = (float*)d_out;

    __nv_bfloat16 *qkvh, *qkvl;
    __half *Xh, *Xl, *A2h, *A2l, *Wq, *Wo;
    cudaGetSymbolAddress((void**)&qkvh, g_qkvh);
    cudaGetSymbolAddress((void**)&qkvl, g_qkvl);
    cudaGetSymbolAddress((void**)&Xh,  g_Xh);
    cudaGetSymbolAddress((void**)&Xl,  g_Xl);
    cudaGetSymbolAddress((void**)&A2h, g_A2h);
    cudaGetSymbolAddress((void**)&A2l, g_A2l);
    cudaGetSymbolAddress((void**)&Wq,  g_Wq);
    cudaGetSymbolAddress((void**)&Wo,  g_Wo);

    cudaFuncSetAttribute(gemm2h,
                         cudaFuncAttributeMaxDynamicSharedMemorySize, GEMM2_SMEM);
    cudaFuncSetAttribute(flash_mma,
                         cudaFuncAttributeMaxDynamicSharedMemorySize, FL_SMEM);

    // Input/weight conversions
    k_split_h2<<<(MROWS * KDIM) / 1024, 256>>>(x, Xh, Xl, MROWS * KDIM);
    k_splitT_h1<<<dim3(QKV3 / 32, KDIM / 32), 256>>>(Wqkv, Wq, KDIM, QKV3);
    k_splitT_h1<<<dim3(D_ / 32, KDIM / 32), 256>>>(Wout, Wo, KDIM, D_);

    // 1) QKV projection (fp16 2-term) -> bf16 hi/lo; dead tiles skipped
    gemm2h<<<dim3(32, MROWS / 128), 256, GEMM2_SMEM>>>(
        Xh, Xl, Wq, bqkv, nullptr, qkvh, qkvl, QKV3, 1);
    fix_globalqkv<<<16, 128>>>(x, Wqkv, bqkv, qkvh, qkvl);

    // 2) Attention (full + windowed fused) + global heads -> fp16 hi/lo attn
    flash_mma<<<dim3(S_ / 64, B_ * (NFULL + NLOCAL)), 128, FL_SMEM>>>(
        qkvh, qkvl, A2h, A2l);
    global_attn<<<(B_ * 2 * S_) / 8, 256>>>(qkvh, qkvl, A2h, A2l);

    // 3) Output projection (fp16 2-term) -> fp32 final
    gemm2h<<<dim3(D_ / 128, MROWS / 128), 256, GEMM2_SMEM>>>(
        A2h, A2l, Wo, bout, out, nullptr, nullptr, D_, 0);
}

// round 14
// speedup vs baseline: 1.4330x; 1.2187x over previous
#include <cuda_runtime.h>
#include <cuda_bf16.h>
#include <cuda_fp16.h>
#include <stdint.h>
#include <math.h>

#define B_    2
#define S_    2048
#define D_    1536
#define QKV3  4608
#define HD_   128
#define NFULL 6
#define NLOCAL 4
#define HWIN  32
#define SCALE 0.08838834764831845f   // 1/sqrt(128)
#define KDIM  1536
#define MROWS 4096                   // B_*S_

// ---------------------------------------------------------------------------
// Scratch (device globals: allocation-free)
// ---------------------------------------------------------------------------
__device__ __half g_qkvh[(size_t)MROWS * QKV3];   // qkv hi (fp16)
__device__ __half g_qkvl[(size_t)MROWS * QKV3];   // qkv lo (fp16)
__device__ __half g_Xh[(size_t)MROWS * KDIM];     // x 2-term
__device__ __half g_Xl[(size_t)MROWS * KDIM];
__device__ __half g_A2h[(size_t)MROWS * KDIM];    // attn out 2-term
__device__ __half g_A2l[(size_t)MROWS * KDIM];
__device__ __half g_Wq[(size_t)QKV3 * KDIM];      // weights 1-term [N][K]
__device__ __half g_Wo[(size_t)D_ * KDIM];

// ---------------------------------------------------------------------------
// PTX helpers (sm_80-baseline: legal on plain compute_103 target)
// ---------------------------------------------------------------------------
__device__ __forceinline__ uint32_t smem_u32(const void* p) {
    uint32_t a;
    asm("{ .reg .u64 t; cvta.to.shared.u64 t, %1; cvt.u32.u64 %0, t; }"
        : "=r"(a) : "l"(p));
    return a;
}
__device__ __forceinline__ void cp16(uint32_t d, const void* s) {
    asm volatile("cp.async.cg.shared.global [%0], [%1], 16;" :: "r"(d), "l"(s));
}
#define CP_COMMIT() asm volatile("cp.async.commit_group;" ::: "memory")

__device__ __forceinline__ void ldm_x4(uint32_t* r, uint32_t addr) {
    asm volatile("ldmatrix.sync.aligned.m8n8.x4.shared.b16 {%0,%1,%2,%3}, [%4];"
                 : "=r"(r[0]), "=r"(r[1]), "=r"(r[2]), "=r"(r[3]) : "r"(addr));
}
__device__ __forceinline__ void ldm_x2(uint32_t* r, uint32_t addr) {
    asm volatile("ldmatrix.sync.aligned.m8n8.x2.shared.b16 {%0,%1}, [%2];"
                 : "=r"(r[0]), "=r"(r[1]) : "r"(addr));
}
__device__ __forceinline__ void ldm_x2t(uint32_t* r, uint32_t addr) {
    asm volatile("ldmatrix.sync.aligned.m8n8.x2.trans.shared.b16 {%0,%1}, [%2];"
                 : "=r"(r[0]), "=r"(r[1]) : "r"(addr));
}
// fp16 mma, fp32 accum
__device__ __forceinline__ void mma16816h(float* c, const uint32_t* a,
                                          const uint32_t* b) {
    asm volatile(
        "mma.sync.aligned.m16n8k16.row.col.f32.f16.f16.f32 "
        "{%0,%1,%2,%3}, {%4,%5,%6,%7}, {%8,%9}, {%0,%1,%2,%3};"
        : "+f"(c[0]), "+f"(c[1]), "+f"(c[2]), "+f"(c[3])
        : "r"(a[0]), "r"(a[1]), "r"(a[2]), "r"(a[3]), "r"(b[0]), "r"(b[1]));
}
// pack two f32 -> f16x2 (first arg -> low half / lower address)
__device__ __forceinline__ uint32_t packh(float lo, float hi) {
    uint32_t r;
    asm("cvt.rn.f16x2.f32 %0, %1, %2;" : "=r"(r) : "f"(hi), "f"(lo));
    return r;
}
__device__ __forceinline__ float h2f(float p) {
    return __half2float(__float2half(p));
}

// ---------------------------------------------------------------------------
// Split kernels
// ---------------------------------------------------------------------------
// fp32 -> fp16 (hi, lo) 2-term
__global__ __launch_bounds__(256) void k_split_h2(
    const float* __restrict__ in, __half* __restrict__ hi,
    __half* __restrict__ lo, int n)
{
    int i = (blockIdx.x * 256 + threadIdx.x) * 4;
    if (i >= n) return;
    float4 v = *(const float4*)(in + i);
    uint32_t* hp = (uint32_t*)(hi + i);
    uint32_t* lp = (uint32_t*)(lo + i);
    hp[0] = packh(v.x, v.y);
    hp[1] = packh(v.z, v.w);
    lp[0] = packh(v.x - h2f(v.x), v.y - h2f(v.y));
    lp[1] = packh(v.z - h2f(v.z), v.w - h2f(v.w));
}

// fp32 [K,N] -> fp16 [N,K] single-term transposed
__global__ __launch_bounds__(256) void k_splitT_h1(
    const float* __restrict__ in, __half* __restrict__ hi, int Kd, int Nd)
{
    __shared__ float t[32][33];
    const int n0 = blockIdx.x * 32, k0 = blockIdx.y * 32;
    const int tx = threadIdx.x & 31, ty = threadIdx.x >> 5;
#pragma unroll
    for (int j = 0; j < 32; j += 8)
        t[ty + j][tx] = in[(size_t)(k0 + ty + j) * Nd + n0 + tx];
    __syncthreads();
#pragma unroll
    for (int j = 0; j < 32; j += 8)
        hi[(size_t)(n0 + ty + j) * Kd + k0 + tx] = __float2half(t[tx][ty + j]);
}

// ---------------------------------------------------------------------------
// Fixup: exact fp32 dot products for the 4 skipped global-head K/V column
// tiles at the only 4 rows global_attn reads.
// ---------------------------------------------------------------------------
__global__ __launch_bounds__(128) void fix_globalqkv(
    const float* __restrict__ x, const float* __restrict__ Wqkv,
    const float* __restrict__ bqkv,
    __half* __restrict__ qkvh, __half* __restrict__ qkvl)
{
    __shared__ float xs[KDIM];
    const int rows[4] = {0, S_ - 1, S_, 2 * S_ - 1};
    const int cols[4] = {2816, 2944, 4352, 4480};
    const int row = rows[blockIdx.x >> 2];
    const int c   = cols[blockIdx.x & 3] + threadIdx.x;

    for (int k = threadIdx.x; k < KDIM; k += 128)
        xs[k] = x[(size_t)row * KDIM + k];
    __syncthreads();

    float s = 0.f;
#pragma unroll 8
    for (int k = 0; k < KDIM; k++)
        s += xs[k] * Wqkv[(size_t)k * QKV3 + c];
    s += bqkv[c];

    const size_t o = (size_t)row * QKV3 + c;
    const __half h = __float2half(s);
    qkvh[o] = h;
    qkvl[o] = __float2half(s - __half2float(h));
}

// ---------------------------------------------------------------------------
// FP16 2-term GEMM: acc = Ah@B^T + Al@B^T + bias.
// A: [M][K] fp16 hi/lo. B: [N][K] fp16. 128x128 tile, BK=32, 8 warps (2x4),
// 2-stage cp.async, 2 CTAs/SM.
// mode 0: write fp32 C. mode 1: write fp16 hi/lo (Ch, Cl) and remap
// blockIdx.x to skip the 4 dead global-head column tiles {22,23,34,35}.
// ---------------------------------------------------------------------------
#define NCH    (KDIM / 32)          // 48
#define AROWB  80
#define TILEB  (128 * AROWB)        // 10240
#define STAGE2 (3 * TILEB)          // 30720
#define GEMM2_SMEM (2 * STAGE2)     // 61440

__global__ __launch_bounds__(256, 2) void gemm2h(
    const __half* __restrict__ Ahg, const __half* __restrict__ Alg,
    const __half* __restrict__ Bg,
    const float* __restrict__ bias, float* __restrict__ C,
    __half* __restrict__ Ch, __half* __restrict__ Cl,
    int Ncols, int mode)
{
    extern __shared__ char smem[];
    const uint32_t sb = smem_u32(smem);
    const int tid  = threadIdx.x;
    const int wid  = tid >> 5;
    const int lane = tid & 31;
    const int warp_m = wid & 1;
    const int warp_n = wid >> 1;
    const int m0 = blockIdx.y * 128;
    int bx = blockIdx.x;
    if (mode == 1 && bx >= 22) bx += 2;   // skip dead tiles 22,23 (34,35 off-grid)
    const int n0 = bx * 128;

    const char* gAh = (const char*)(Ahg + (size_t)m0 * KDIM);
    const char* gAl = (const char*)(Alg + (size_t)m0 * KDIM);
    const char* gB  = (const char*)(Bg  + (size_t)n0 * KDIM);

    float acc[4][4][4];
#pragma unroll
    for (int i = 0; i < 4; i++)
#pragma unroll
        for (int j = 0; j < 4; j++)
#pragma unroll
            for (int k = 0; k < 4; k++) acc[i][j][k] = 0.f;

#define LOAD_CHUNK2(ch, stage) do {                                            \
        const uint32_t st = sb + (stage) * STAGE2;                             \
        const size_t kb = (size_t)(ch) * 64;                                   \
        _Pragma("unroll")                                                      \
        for (int t = 0; t < 6; t++) {                                          \
            const int u = tid + t * 256;                                       \
            const int tile = u >> 9;                                           \
            const int r = (u >> 2) & 127;                                      \
            const int c = u & 3;                                               \
            const char* g = (tile == 0) ? gAh : (tile == 1) ? gAl : gB;        \
            cp16(st + tile * TILEB + r * AROWB + c * 16,                       \
                 g + (size_t)r * (KDIM * 2) + kb + c * 16);                    \
        }                                                                      \
        CP_COMMIT();                                                           \
    } while (0)

    LOAD_CHUNK2(0, 0);
    LOAD_CHUNK2(1, 1);

    const int a_row  = warp_m * 64 + (lane & 15);
    const int a_koff = (lane >> 4) * 16;
    const int b_row  = warp_n * 32 + (lane & 7);
    const int b_koff = ((lane >> 3) & 1) * 16;

    for (int i = 0; i < NCH; i++) {
        const int p = i & 1;
        if (i + 1 < NCH) asm volatile("cp.async.wait_group 1;" ::: "memory");
        else             asm volatile("cp.async.wait_group 0;" ::: "memory");
        __syncthreads();

        const uint32_t sAh = sb + p * STAGE2;
        const uint32_t sAl = sAh + TILEB;
        const uint32_t sBh = sAh + 2 * TILEB;

#pragma unroll
        for (int kk = 0; kk < 2; kk++) {
            uint32_t bh[4][2];
#pragma unroll
            for (int nf = 0; nf < 4; nf++) {
                const uint32_t off = (b_row + nf * 8) * AROWB + kk * 32 + b_koff;
                ldm_x2(bh[nf], sBh + off);
            }
#pragma unroll
            for (int mf = 0; mf < 4; mf++) {
                uint32_t ah[4], al[4];
                const uint32_t off = (a_row + mf * 16) * AROWB + kk * 32 + a_koff;
                ldm_x4(ah, sAh + off);
                ldm_x4(al, sAl + off);
#pragma unroll
                for (int nf = 0; nf < 4; nf++) mma16816h(acc[mf][nf], ah, bh[nf]);
#pragma unroll
                for (int nf = 0; nf < 4; nf++) mma16816h(acc[mf][nf], al, bh[nf]);
            }
        }
        __syncthreads();
        if (i + 2 < NCH) LOAD_CHUNK2(i + 2, p);
        else CP_COMMIT();
    }

    const int g_  = lane >> 2;
    const int tg  = lane & 3;
#pragma unroll
    for (int mf = 0; mf < 4; mf++) {
        const int row = m0 + warp_m * 64 + mf * 16 + g_;
#pragma unroll
        for (int nf = 0; nf < 4; nf++) {
            const int col = n0 + warp_n * 32 + nf * 8 + tg * 2;
            const float b0 = bias[col], b1 = bias[col + 1];
            const float v00 = acc[mf][nf][0] + b0, v01 = acc[mf][nf][1] + b1;
            const float v10 = acc[mf][nf][2] + b0, v11 = acc[mf][nf][3] + b1;
            if (mode == 0) {
                *(float2*)(C + (size_t)row * Ncols + col) = make_float2(v00, v01);
                *(float2*)(C + (size_t)(row + 8) * Ncols + col) = make_float2(v10, v11);
            } else {
                const size_t o0 = (size_t)row * Ncols + col;
                const size_t o1 = (size_t)(row + 8) * Ncols + col;
                *(uint32_t*)(Ch + o0) = packh(v00, v01);
                *(uint32_t*)(Ch + o1) = packh(v10, v11);
                *(uint32_t*)(Cl + o0) = packh(v00 - h2f(v00), v01 - h2f(v01));
                *(uint32_t*)(Cl + o1) = packh(v10 - h2f(v10), v11 - h2f(v11));
            }
        }
    }
}

// ---------------------------------------------------------------------------
// Flash attention, fp16 2-term: S = Qh@Kh + Ql@Kh, O = Ph@Vh + Pl@Vh.
// Mq=64, Nk=64, hd=128. V natural + ldmatrix.trans. Smem: Qh,Ql,Kh,Vh only
// (68 KB -> up to 3 CTAs/SM). K/V prefetched intra-tile via cp.async.
// Writes fp16 hi/lo attn output.
// ---------------------------------------------------------------------------
#define FQSTR 272                 // row stride bytes (128 fp16 + 8 pad)
#define FQB   (64 * FQSTR)        // 17408
#define FL_SMEM (4 * FQB)         // 69632

__global__ __launch_bounds__(128) void flash_mma(
    const __half* __restrict__ qh, const __half* __restrict__ ql,
    __half* __restrict__ attnh, __half* __restrict__ attnl)
{
    extern __shared__ char smem[];
    const uint32_t sb  = smem_u32(smem);
    const uint32_t sQh = sb,            sQl = sb + FQB;
    const uint32_t sKh = sb + 2 * FQB,  sVh = sb + 3 * FQB;

    const int tid = threadIdx.x, wid = tid >> 5, lane = tid & 31;
    const int g = lane >> 2, t = lane & 3;

    int yy = blockIdx.y, b, h, win;
    if (yy < B_ * NFULL) { b = yy / NFULL;  h = yy % NFULL;          win = 0; }
    else { yy -= B_ * NFULL; b = yy / NLOCAL; h = NFULL + yy % NLOCAL; win = 1; }
    const int q0 = blockIdx.x * 64;

    const size_t rb   = (size_t)b * S_ * QKV3 + (size_t)h * HD_;
    const size_t koff = rb + 1536;
    const size_t voff = rb + 3072;

    int kt0 = 0, kt1 = S_ >> 6;
    if (win) {
        kt0 = (q0 >= HWIN) ? ((q0 - HWIN) >> 6) : 0;
        kt1 = min(kt1, ((q0 + 63 + HWIN) >> 6) + 1);
    }

    // Q tiles (hi+lo, once) + first K/V hi tiles
    for (int u = tid; u < 1024; u += 128) {
        const int r = u >> 4, c = u & 15;
        const size_t go = rb + (size_t)(q0 + r) * QKV3 + c * 8;
        cp16(sQh + r * FQSTR + c * 16, qh + go);
        cp16(sQl + r * FQSTR + c * 16, ql + go);
    }
    {
        const int k0 = kt0 << 6;
        for (int u = tid; u < 1024; u += 128) {
            const int r = u >> 4, c = u & 15;
            cp16(sKh + r * FQSTR + c * 16, qh + koff + (size_t)(k0 + r) * QKV3 + c * 8);
            cp16(sVh + r * FQSTR + c * 16, qh + voff + (size_t)(k0 + r) * QKV3 + c * 8);
        }
    }
    CP_COMMIT();

    float oacc[16][4];
#pragma unroll
    for (int i = 0; i < 16; i++)
#pragma unroll
        for (int j = 0; j < 4; j++) oacc[i][j] = 0.f;
    float m0 = -1e30f, m1 = -1e30f, l0 = 0.f, l1 = 0.f;

    const int a_row  = wid * 16 + (lane & 15);
    const int a_koff = (lane >> 4) * 16;
    const int b_r    = lane & 7;
    const int b_koff = ((lane >> 3) & 1) * 16;
    const int v_row  = lane & 15;          // trans ldmatrix row (key)
    const int row0   = q0 + wid * 16 + g;

    for (int kt = kt0; kt < kt1; kt++) {
        const int k0 = kt << 6;
        asm volatile("cp.async.wait_group 0;" ::: "memory");
        __syncthreads();

        // S = Qh@Kh + Ql@Kh
        float sacc[8][4];
#pragma unroll
        for (int i = 0; i < 8; i++)
#pragma unroll
            for (int j = 0; j < 4; j++) sacc[i][j] = 0.f;
#pragma unroll
        for (int kc = 0; kc < 8; kc++) {
            uint32_t qah[4], qal[4];
            const uint32_t aoff = a_row * FQSTR + kc * 32 + a_koff;
            ldm_x4(qah, sQh + aoff);
            ldm_x4(qal, sQl + aoff);
#pragma unroll
            for (int np = 0; np < 4; np++) {
                const int n0f = 2 * np, n1f = n0f + 1;
                uint32_t kbh0[2], kbh1[2];
                const uint32_t bo0 = (n0f * 8 + b_r) * FQSTR + kc * 32 + b_koff;
                const uint32_t bo1 = (n1f * 8 + b_r) * FQSTR + kc * 32 + b_koff;
                ldm_x2(kbh0, sKh + bo0);
                ldm_x2(kbh1, sKh + bo1);
                mma16816h(sacc[n0f], qah, kbh0);
                mma16816h(sacc[n1f], qah, kbh1);
                mma16816h(sacc[n0f], qal, kbh0);
                mma16816h(sacc[n1f], qal, kbh1);
            }
        }
        __syncthreads();   // all warps done reading K smem

        // prefetch next K while softmax+PV run
        if (kt + 1 < kt1) {
            const int kn = (kt + 1) << 6;
            for (int u = tid; u < 1024; u += 128) {
                const int r = u >> 4, c = u & 15;
                cp16(sKh + r * FQSTR + c * 16,
                     qh + koff + (size_t)(kn + r) * QKV3 + c * 8);
            }
            CP_COMMIT();
        }

        // scale + mask + online softmax
        float mt0 = -1e30f, mt1 = -1e30f;
#pragma unroll
        for (int nf = 0; nf < 8; nf++) {
#pragma unroll
            for (int e = 0; e < 4; e++) {
                float v = sacc[nf][e] * SCALE;
                if (win) {
                    const int col = k0 + nf * 8 + 2 * t + (e & 1);
                    const int row = row0 + (e >> 1) * 8;
                    const int dq = row - col;
                    if (dq > HWIN || dq < -HWIN) v = -1e30f;
                }
                sacc[nf][e] = v;
            }
            mt0 = fmaxf(mt0, fmaxf(sacc[nf][0], sacc[nf][1]));
            mt1 = fmaxf(mt1, fmaxf(sacc[nf][2], sacc[nf][3]));
        }
        mt0 = fmaxf(mt0, __shfl_xor_sync(0xffffffffu, mt0, 1));
        mt0 = fmaxf(mt0, __shfl_xor_sync(0xffffffffu, mt0, 2));
        mt1 = fmaxf(mt1, __shfl_xor_sync(0xffffffffu, mt1, 1));
        mt1 = fmaxf(mt1, __shfl_xor_sync(0xffffffffu, mt1, 2));
        const float mn0 = fmaxf(m0, mt0), mn1 = fmaxf(m1, mt1);
        const float al0 = __expf(m0 - mn0), al1 = __expf(m1 - mn1);
        m0 = mn0; m1 = mn1;
        l0 *= al0; l1 *= al1;
#pragma unroll
        for (int dn = 0; dn < 16; dn++) {
            oacc[dn][0] *= al0; oacc[dn][1] *= al0;
            oacc[dn][2] *= al1; oacc[dn][3] *= al1;
        }

        // P = exp(S - m), fp16 hi/lo split in registers
        uint32_t pah[4][4], pal[4][4];
#pragma unroll
        for (int c = 0; c < 4; c++) {
            float p0 = __expf(sacc[2 * c][0] - mn0);
            float p1 = __expf(sacc[2 * c][1] - mn0);
            float p2 = __expf(sacc[2 * c][2] - mn1);
            float p3 = __expf(sacc[2 * c][3] - mn1);
            float r0 = __expf(sacc[2 * c + 1][0] - mn0);
            float r1 = __expf(sacc[2 * c + 1][1] - mn0);
            float r2 = __expf(sacc[2 * c + 1][2] - mn1);
            float r3 = __expf(sacc[2 * c + 1][3] - mn1);
            l0 += p0 + p1 + r0 + r1;
            l1 += p2 + p3 + r2 + r3;
            pah[c][0] = packh(p0, p1);
            pah[c][1] = packh(p2, p3);
            pah[c][2] = packh(r0, r1);
            pah[c][3] = packh(r2, r3);
            pal[c][0] = packh(p0 - h2f(p0), p1 - h2f(p1));
            pal[c][1] = packh(p2 - h2f(p2), p3 - h2f(p3));
            pal[c][2] = packh(r0 - h2f(r0), r1 - h2f(r1));
            pal[c][3] = packh(r2 - h2f(r2), r3 - h2f(r3));
        }

        // O += Ph@Vh + Pl@Vh; V natural, trans ldmatrix
#pragma unroll
        for (int c = 0; c < 4; c++) {
#pragma unroll
            for (int dp = 0; dp < 8; dp++) {
                const int d0 = 2 * dp, d1 = d0 + 1;
                uint32_t vbh0[2], vbh1[2];
                const uint32_t vo0 = (c * 16 + v_row) * FQSTR + d0 * 16;
                const uint32_t vo1 = (c * 16 + v_row) * FQSTR + d1 * 16;
                ldm_x2t(vbh0, sVh + vo0);
                ldm_x2t(vbh1, sVh + vo1);
                mma16816h(oacc[d0], pah[c], vbh0);
                mma16816h(oacc[d1], pah[c], vbh1);
                mma16816h(oacc[d0], pal[c], vbh0);
                mma16816h(oacc[d1], pal[c], vbh1);
            }
        }
        __syncthreads();   // all warps done reading V smem

        if (kt + 1 < kt1) {
            const int kn = (kt + 1) << 6;
            for (int u = tid; u < 1024; u += 128) {
                const int r = u >> 4, c = u & 15;
                cp16(sVh + r * FQSTR + c * 16,
                     qh + voff + (size_t)(kn + r) * QKV3 + c * 8);
            }
            CP_COMMIT();
        }
    }

    // finalize: reduce l across t-group, normalize, write fp16 hi/lo
    l0 += __shfl_xor_sync(0xffffffffu, l0, 1);
    l0 += __shfl_xor_sync(0xffffffffu, l0, 2);
    l1 += __shfl_xor_sync(0xffffffffu, l1, 1);
    l1 += __shfl_xor_sync(0xffffffffu, l1, 2);
    const float inv0 = 1.f / l0, inv1 = 1.f / l1;

    const size_t ob0 = ((size_t)b * S_ + row0) * D_ + h * HD_;
    const size_t ob1 = ob0 + 8 * D_;
#pragma unroll
    for (int dn = 0; dn < 16; dn++) {
        const int col = dn * 8 + 2 * t;
        const float v00 = oacc[dn][0] * inv0, v01 = oacc[dn][1] * inv0;
        const float v10 = oacc[dn][2] * inv1, v11 = oacc[dn][3] * inv1;
        *(uint32_t*)(attnh + ob0 + col) = packh(v00, v01);
        *(uint32_t*)(attnh + ob1 + col) = packh(v10, v11);
        *(uint32_t*)(attnl + ob0 + col) = packh(v00 - h2f(v00), v01 - h2f(v01));
        *(uint32_t*)(attnl + ob1 + col) = packh(v10 - h2f(v10), v11 - h2f(v11));
    }
}

// ---------------------------------------------------------------------------
// Global heads: qkv reconstructed from fp16 hi+lo; writes fp16 hi/lo attn.
// ---------------------------------------------------------------------------
__global__ __launch_bounds__(256) void global_attn(
    const __half* __restrict__ qh, const __half* __restrict__ ql,
    __half* __restrict__ attnh, __half* __restrict__ attnl)
{
    const int wip  = threadIdx.x >> 5;
    const int lane = threadIdx.x & 31;
    const int wid  = blockIdx.x * 8 + wip;
    const int q  = wid & (S_ - 1);
    const int hg = (wid >> 11) & 1;
    const int b  = wid >> 12;
    const int h  = NFULL + NLOCAL + hg;

    const size_t base = (size_t)b * S_ * QKV3 + (size_t)h * HD_;
    const size_t qp  = base + (size_t)q * QKV3;
    const size_t kp0 = base + 1536;
    const size_t kp1 = base + 1536 + (size_t)(S_ - 1) * QKV3;
    const size_t vp0 = base + 3072;
    const size_t vp1 = base + 3072 + (size_t)(S_ - 1) * QKV3;

#define RD(off, d) (__half2float(qh[(off) + (d)]) + __half2float(ql[(off) + (d)]))

    float s0 = 0.f, s1 = 0.f;
#pragma unroll
    for (int c = 0; c < 4; c++) {
        const int d = lane + (c << 5);
        const float qd = RD(qp, d);
        s0 += qd * RD(kp0, d);
        s1 += qd * RD(kp1, d);
    }
#pragma unroll
    for (int o = 16; o > 0; o >>= 1) {
        s0 += __shfl_xor_sync(0xffffffffu, s0, o);
        s1 += __shfl_xor_sync(0xffffffffu, s1, o);
    }
    s0 *= SCALE; s1 *= SCALE;
    const float mx = fmaxf(s0, s1);
    float e0 = __expf(s0 - mx), e1 = __expf(s1 - mx);
    const float inv = 1.f / (e0 + e1);
    e0 *= inv; e1 *= inv;

    const size_t op = ((size_t)b * S_ + q) * D_ + h * HD_;
#pragma unroll
    for (int c = 0; c < 4; c++) {
        const int d = lane + (c << 5);
        const float o = e0 * RD(vp0, d) + e1 * RD(vp1, d);
        const __half oh = __float2half(o);
        attnh[op + d] = oh;
        attnl[op + d] = __float2half(o - __half2float(oh));
    }
#undef RD
}

// ---------------------------------------------------------------------------
extern "C" void kernel_launch(void* const* d_in, const int* in_sizes, int n_in,
                              void* d_out, int out_size)
{
    const float* x    = (const float*)d_in[0];
    const float* Wqkv = (const float*)d_in[1];
    const float* bqkv = (const float*)d_in[2];
    const float* Wout = (const float*)d_in[3];
    const float* bout = (const float*)d_in[4];
    float* out = (float*)d_out;

    __half *qkvh, *qkvl, *Xh, *Xl, *A2h, *A2l, *Wq, *Wo;
    cudaGetSymbolAddress((void**)&qkvh, g_qkvh);
    cudaGetSymbolAddress((void**)&qkvl, g_qkvl);
    cudaGetSymbolAddress((void**)&Xh,  g_Xh);
    cudaGetSymbolAddress((void**)&Xl,  g_Xl);
    cudaGetSymbolAddress((void**)&A2h, g_A2h);
    cudaGetSymbolAddress((void**)&A2l, g_A2l);
    cudaGetSymbolAddress((void**)&Wq,  g_Wq);
    cudaGetSymbolAddress((void**)&Wo,  g_Wo);

    cudaFuncSetAttribute(gemm2h,
                         cudaFuncAttributeMaxDynamicSharedMemorySize, GEMM2_SMEM);
    cudaFuncSetAttribute(flash_mma,
                         cudaFuncAttributeMaxDynamicSharedMemorySize, FL_SMEM);

    // Input/weight conversions
    k_split_h2<<<(MROWS * KDIM) / 1024, 256>>>(x, Xh, Xl, MROWS * KDIM);
    k_splitT_h1<<<dim3(QKV3 / 32, KDIM / 32), 256>>>(Wqkv, Wq, KDIM, QKV3);
    k_splitT_h1<<<dim3(D_ / 32, KDIM / 32), 256>>>(Wout, Wo, KDIM, D_);

    // 1) QKV projection (fp16 2-term) -> fp16 hi/lo; dead tiles skipped
    gemm2h<<<dim3(32, MROWS / 128), 256, GEMM2_SMEM>>>(
        Xh, Xl, Wq, bqkv, nullptr, qkvh, qkvl, QKV3, 1);
    fix_globalqkv<<<16, 128>>>(x, Wqkv, bqkv, qkvh, qkvl);

    // 2) Attention (full + windowed fused) + global heads -> fp16 hi/lo attn
    flash_mma<<<dim3(S_ / 64, B_ * (NFULL + NLOCAL)), 128, FL_SMEM>>>(
        qkvh, qkvl, A2h, A2l);
    global_attn<<<(B_ * 2 * S_) / 8, 256>>>(qkvh, qkvl, A2h, A2l);

    // 3) Output projection (fp16 2-term) -> fp32 final
    gemm2h<<<dim3(D_ / 128, MROWS / 128), 256, GEMM2_SMEM>>>(
        A2h, A2l, Wo, bout, out, nullptr, nullptr, D_, 0);
}

// round 15
// speedup vs baseline: 1.9115x; 1.3339x over previous
#include <cuda_runtime.h>
#include <cuda_bf16.h>
#include <cuda_fp16.h>
#include <stdint.h>
#include <math.h>

#define B_    2
#define S_    2048
#define D_    1536
#define QKV3  4608
#define HD_   128
#define NFULL 6
#define NLOCAL 4
#define HWIN  32
#define SCALE 0.08838834764831845f   // 1/sqrt(128)
#define KDIM  1536
#define MROWS 4096                   // B_*S_

// ---------------------------------------------------------------------------
// Scratch (device globals: allocation-free)
// ---------------------------------------------------------------------------
__device__ __half g_qkvh[(size_t)MROWS * QKV3];   // qkv hi (fp16)
__device__ __half g_qkvl[(size_t)MROWS * QKV3];   // qkv lo (fp16, for flash Q)
__device__ __half g_X1[(size_t)MROWS * KDIM];     // x, fp16 1-term
__device__ __half g_A21[(size_t)MROWS * KDIM];    // attn out, fp16 1-term
__device__ __half g_Wq[(size_t)QKV3 * KDIM];      // weights 1-term [N][K]
__device__ __half g_Wo[(size_t)D_ * KDIM];

// ---------------------------------------------------------------------------
// PTX helpers (sm_80-baseline: legal on plain compute_103 target)
// ---------------------------------------------------------------------------
__device__ __forceinline__ uint32_t smem_u32(const void* p) {
    uint32_t a;
    asm("{ .reg .u64 t; cvta.to.shared.u64 t, %1; cvt.u32.u64 %0, t; }"
        : "=r"(a) : "l"(p));
    return a;
}
__device__ __forceinline__ void cp16(uint32_t d, const void* s) {
    asm volatile("cp.async.cg.shared.global [%0], [%1], 16;" :: "r"(d), "l"(s));
}
#define CP_COMMIT() asm volatile("cp.async.commit_group;" ::: "memory")

__device__ __forceinline__ void ldm_x4(uint32_t* r, uint32_t addr) {
    asm volatile("ldmatrix.sync.aligned.m8n8.x4.shared.b16 {%0,%1,%2,%3}, [%4];"
                 : "=r"(r[0]), "=r"(r[1]), "=r"(r[2]), "=r"(r[3]) : "r"(addr));
}
__device__ __forceinline__ void ldm_x2(uint32_t* r, uint32_t addr) {
    asm volatile("ldmatrix.sync.aligned.m8n8.x2.shared.b16 {%0,%1}, [%2];"
                 : "=r"(r[0]), "=r"(r[1]) : "r"(addr));
}
__device__ __forceinline__ void ldm_x2t(uint32_t* r, uint32_t addr) {
    asm volatile("ldmatrix.sync.aligned.m8n8.x2.trans.shared.b16 {%0,%1}, [%2];"
                 : "=r"(r[0]), "=r"(r[1]) : "r"(addr));
}
// fp16 mma, fp32 accum
__device__ __forceinline__ void mma16816h(float* c, const uint32_t* a,
                                          const uint32_t* b) {
    asm volatile(
        "mma.sync.aligned.m16n8k16.row.col.f32.f16.f16.f32 "
        "{%0,%1,%2,%3}, {%4,%5,%6,%7}, {%8,%9}, {%0,%1,%2,%3};"
        : "+f"(c[0]), "+f"(c[1]), "+f"(c[2]), "+f"(c[3])
        : "r"(a[0]), "r"(a[1]), "r"(a[2]), "r"(a[3]), "r"(b[0]), "r"(b[1]));
}
// pack two f32 -> f16x2 (first arg -> low half / lower address)
__device__ __forceinline__ uint32_t packh(float lo, float hi) {
    uint32_t r;
    asm("cvt.rn.f16x2.f32 %0, %1, %2;" : "=r"(r) : "f"(hi), "f"(lo));
    return r;
}
__device__ __forceinline__ float h2f(float p) {
    return __half2float(__float2half(p));
}

// ---------------------------------------------------------------------------
// Conversion kernels
// ---------------------------------------------------------------------------
// fp32 -> fp16 (single term)
__global__ __launch_bounds__(256) void k_cvt_h1(
    const float* __restrict__ in, __half* __restrict__ hi, int n)
{
    int i = (blockIdx.x * 256 + threadIdx.x) * 4;
    if (i >= n) return;
    float4 v = *(const float4*)(in + i);
    uint32_t* hp = (uint32_t*)(hi + i);
    hp[0] = packh(v.x, v.y);
    hp[1] = packh(v.z, v.w);
}

// fp32 [K,N] -> fp16 [N,K] single-term transposed
__global__ __launch_bounds__(256) void k_splitT_h1(
    const float* __restrict__ in, __half* __restrict__ hi, int Kd, int Nd)
{
    __shared__ float t[32][33];
    const int n0 = blockIdx.x * 32, k0 = blockIdx.y * 32;
    const int tx = threadIdx.x & 31, ty = threadIdx.x >> 5;
#pragma unroll
    for (int j = 0; j < 32; j += 8)
        t[ty + j][tx] = in[(size_t)(k0 + ty + j) * Nd + n0 + tx];
    __syncthreads();
#pragma unroll
    for (int j = 0; j < 32; j += 8)
        hi[(size_t)(n0 + ty + j) * Kd + k0 + tx] = __float2half(t[tx][ty + j]);
}

// ---------------------------------------------------------------------------
// Fixup: exact fp32 dot products for the 4 skipped global-head K/V column
// tiles at the only 4 rows global_attn reads.
// ---------------------------------------------------------------------------
__global__ __launch_bounds__(128) void fix_globalqkv(
    const float* __restrict__ x, const float* __restrict__ Wqkv,
    const float* __restrict__ bqkv,
    __half* __restrict__ qkvh, __half* __restrict__ qkvl)
{
    __shared__ float xs[KDIM];
    const int rows[4] = {0, S_ - 1, S_, 2 * S_ - 1};
    const int cols[4] = {2816, 2944, 4352, 4480};
    const int row = rows[blockIdx.x >> 2];
    const int c   = cols[blockIdx.x & 3] + threadIdx.x;

    for (int k = threadIdx.x; k < KDIM; k += 128)
        xs[k] = x[(size_t)row * KDIM + k];
    __syncthreads();

    float s = 0.f;
#pragma unroll 8
    for (int k = 0; k < KDIM; k++)
        s += xs[k] * Wqkv[(size_t)k * QKV3 + c];
    s += bqkv[c];

    const size_t o = (size_t)row * QKV3 + c;
    const __half h = __float2half(s);
    qkvh[o] = h;
    qkvl[o] = __float2half(s - __half2float(h));
}

// ---------------------------------------------------------------------------
// FP16 1-term GEMM: acc = A@B^T + bias.
// A: [M][K] fp16. B: [N][K] fp16. 128x128 tile, BK=32, 8 warps (2x4),
// 2-stage cp.async, 2 CTAs/SM. Smem/stage = 2 tiles x 10240 = 20480.
// mode 0: write fp32 C. mode 1: write fp16 hi/lo (Ch, Cl) and remap
// blockIdx.x to skip the 4 dead global-head column tiles {22,23,34,35}.
// ---------------------------------------------------------------------------
#define NCH    (KDIM / 32)          // 48
#define AROWB  80
#define TILEB  (128 * AROWB)        // 10240
#define STAGE1 (2 * TILEB)          // 20480
#define GEMM1_SMEM (2 * STAGE1)     // 40960

__global__ __launch_bounds__(256, 2) void gemm1h(
    const __half* __restrict__ Ag, const __half* __restrict__ Bg,
    const float* __restrict__ bias, float* __restrict__ C,
    __half* __restrict__ Ch, __half* __restrict__ Cl,
    int Ncols, int mode)
{
    extern __shared__ char smem[];
    const uint32_t sb = smem_u32(smem);
    const int tid  = threadIdx.x;
    const int wid  = tid >> 5;
    const int lane = tid & 31;
    const int warp_m = wid & 1;
    const int warp_n = wid >> 1;
    const int m0 = blockIdx.y * 128;
    int bx = blockIdx.x;
    if (mode == 1 && bx >= 22) bx += 2;   // skip dead tiles 22,23 (34,35 off-grid)
    const int n0 = bx * 128;

    const char* gA = (const char*)(Ag + (size_t)m0 * KDIM);
    const char* gB = (const char*)(Bg + (size_t)n0 * KDIM);

    float acc[4][4][4];
#pragma unroll
    for (int i = 0; i < 4; i++)
#pragma unroll
        for (int j = 0; j < 4; j++)
#pragma unroll
            for (int k = 0; k < 4; k++) acc[i][j][k] = 0.f;

    // 1024 16B-units per chunk (2 tiles x 128 rows x 4 segs) / 256 thr = 4
#define LOAD_CHUNK1(ch, stage) do {                                            \
        const uint32_t st = sb + (stage) * STAGE1;                             \
        const size_t kb = (size_t)(ch) * 64;                                   \
        _Pragma("unroll")                                                      \
        for (int t = 0; t < 4; t++) {                                          \
            const int u = tid + t * 256;                                       \
            const int tile = u >> 9;                                           \
            const int r = (u >> 2) & 127;                                      \
            const int c = u & 3;                                               \
            const char* g = (tile == 0) ? gA : gB;                             \
            cp16(st + tile * TILEB + r * AROWB + c * 16,                       \
                 g + (size_t)r * (KDIM * 2) + kb + c * 16);                    \
        }                                                                      \
        CP_COMMIT();                                                           \
    } while (0)

    LOAD_CHUNK1(0, 0);
    LOAD_CHUNK1(1, 1);

    const int a_row  = warp_m * 64 + (lane & 15);
    const int a_koff = (lane >> 4) * 16;
    const int b_row  = warp_n * 32 + (lane & 7);
    const int b_koff = ((lane >> 3) & 1) * 16;

    for (int i = 0; i < NCH; i++) {
        const int p = i & 1;
        if (i + 1 < NCH) asm volatile("cp.async.wait_group 1;" ::: "memory");
        else             asm volatile("cp.async.wait_group 0;" ::: "memory");
        __syncthreads();

        const uint32_t sA = sb + p * STAGE1;
        const uint32_t sB = sA + TILEB;

#pragma unroll
        for (int kk = 0; kk < 2; kk++) {
            uint32_t bh[4][2];
#pragma unroll
            for (int nf = 0; nf < 4; nf++) {
                const uint32_t off = (b_row + nf * 8) * AROWB + kk * 32 + b_koff;
                ldm_x2(bh[nf], sB + off);
            }
#pragma unroll
            for (int mf = 0; mf < 4; mf++) {
                uint32_t ah[4];
                const uint32_t off = (a_row + mf * 16) * AROWB + kk * 32 + a_koff;
                ldm_x4(ah, sA + off);
#pragma unroll
                for (int nf = 0; nf < 4; nf++) mma16816h(acc[mf][nf], ah, bh[nf]);
            }
        }
        __syncthreads();
        if (i + 2 < NCH) LOAD_CHUNK1(i + 2, p);
        else CP_COMMIT();
    }

    const int g_  = lane >> 2;
    const int tg  = lane & 3;
#pragma unroll
    for (int mf = 0; mf < 4; mf++) {
        const int row = m0 + warp_m * 64 + mf * 16 + g_;
#pragma unroll
        for (int nf = 0; nf < 4; nf++) {
            const int col = n0 + warp_n * 32 + nf * 8 + tg * 2;
            const float b0 = bias[col], b1 = bias[col + 1];
            const float v00 = acc[mf][nf][0] + b0, v01 = acc[mf][nf][1] + b1;
            const float v10 = acc[mf][nf][2] + b0, v11 = acc[mf][nf][3] + b1;
            if (mode == 0) {
                *(float2*)(C + (size_t)row * Ncols + col) = make_float2(v00, v01);
                *(float2*)(C + (size_t)(row + 8) * Ncols + col) = make_float2(v10, v11);
            } else {
                const size_t o0 = (size_t)row * Ncols + col;
                const size_t o1 = (size_t)(row + 8) * Ncols + col;
                *(uint32_t*)(Ch + o0) = packh(v00, v01);
                *(uint32_t*)(Ch + o1) = packh(v10, v11);
                *(uint32_t*)(Cl + o0) = packh(v00 - h2f(v00), v01 - h2f(v01));
                *(uint32_t*)(Cl + o1) = packh(v10 - h2f(v10), v11 - h2f(v11));
            }
        }
    }
}

// ---------------------------------------------------------------------------
// Flash attention, fp16: S = Qh@Kh + Ql@Kh (2-term Q), O = Ph@Vh + Pl@Vh.
// Mq=64, Nk=64, hd=128. V natural + ldmatrix.trans. Smem: Qh,Ql,Kh,Vh.
// K/V prefetched intra-tile via cp.async. Writes fp16 attn (hi only).
// ---------------------------------------------------------------------------
#define FQSTR 272                 // row stride bytes (128 fp16 + 8 pad)
#define FQB   (64 * FQSTR)        // 17408
#define FL_SMEM (4 * FQB)         // 69632

__global__ __launch_bounds__(128) void flash_mma(
    const __half* __restrict__ qh, const __half* __restrict__ ql,
    __half* __restrict__ attnh)
{
    extern __shared__ char smem[];
    const uint32_t sb  = smem_u32(smem);
    const uint32_t sQh = sb,            sQl = sb + FQB;
    const uint32_t sKh = sb + 2 * FQB,  sVh = sb + 3 * FQB;

    const int tid = threadIdx.x, wid = tid >> 5, lane = tid & 31;
    const int g = lane >> 2, t = lane & 3;

    int yy = blockIdx.y, b, h, win;
    if (yy < B_ * NFULL) { b = yy / NFULL;  h = yy % NFULL;          win = 0; }
    else { yy -= B_ * NFULL; b = yy / NLOCAL; h = NFULL + yy % NLOCAL; win = 1; }
    const int q0 = blockIdx.x * 64;

    const size_t rb   = (size_t)b * S_ * QKV3 + (size_t)h * HD_;
    const size_t koff = rb + 1536;
    const size_t voff = rb + 3072;

    int kt0 = 0, kt1 = S_ >> 6;
    if (win) {
        kt0 = (q0 >= HWIN) ? ((q0 - HWIN) >> 6) : 0;
        kt1 = min(kt1, ((q0 + 63 + HWIN) >> 6) + 1);
    }

    // Q tiles (hi+lo, once) + first K/V hi tiles
    for (int u = tid; u < 1024; u += 128) {
        const int r = u >> 4, c = u & 15;
        const size_t go = rb + (size_t)(q0 + r) * QKV3 + c * 8;
        cp16(sQh + r * FQSTR + c * 16, qh + go);
        cp16(sQl + r * FQSTR + c * 16, ql + go);
    }
    {
        const int k0 = kt0 << 6;
        for (int u = tid; u < 1024; u += 128) {
            const int r = u >> 4, c = u & 15;
            cp16(sKh + r * FQSTR + c * 16, qh + koff + (size_t)(k0 + r) * QKV3 + c * 8);
            cp16(sVh + r * FQSTR + c * 16, qh + voff + (size_t)(k0 + r) * QKV3 + c * 8);
        }
    }
    CP_COMMIT();

    float oacc[16][4];
#pragma unroll
    for (int i = 0; i < 16; i++)
#pragma unroll
        for (int j = 0; j < 4; j++) oacc[i][j] = 0.f;
    float m0 = -1e30f, m1 = -1e30f, l0 = 0.f, l1 = 0.f;

    const int a_row  = wid * 16 + (lane & 15);
    const int a_koff = (lane >> 4) * 16;
    const int b_r    = lane & 7;
    const int b_koff = ((lane >> 3) & 1) * 16;
    const int v_row  = lane & 15;          // trans ldmatrix row (key)
    const int row0   = q0 + wid * 16 + g;

    for (int kt = kt0; kt < kt1; kt++) {
        const int k0 = kt << 6;
        asm volatile("cp.async.wait_group 0;" ::: "memory");
        __syncthreads();

        // S = Qh@Kh + Ql@Kh
        float sacc[8][4];
#pragma unroll
        for (int i = 0; i < 8; i++)
#pragma unroll
            for (int j = 0; j < 4; j++) sacc[i][j] = 0.f;
#pragma unroll
        for (int kc = 0; kc < 8; kc++) {
            uint32_t qah[4], qal[4];
            const uint32_t aoff = a_row * FQSTR + kc * 32 + a_koff;
            ldm_x4(qah, sQh + aoff);
            ldm_x4(qal, sQl + aoff);
#pragma unroll
            for (int np = 0; np < 4; np++) {
                const int n0f = 2 * np, n1f = n0f + 1;
                uint32_t kbh0[2], kbh1[2];
                const uint32_t bo0 = (n0f * 8 + b_r) * FQSTR + kc * 32 + b_koff;
                const uint32_t bo1 = (n1f * 8 + b_r) * FQSTR + kc * 32 + b_koff;
                ldm_x2(kbh0, sKh + bo0);
                ldm_x2(kbh1, sKh + bo1);
                mma16816h(sacc[n0f], qah, kbh0);
                mma16816h(sacc[n1f], qah, kbh1);
                mma16816h(sacc[n0f], qal, kbh0);
                mma16816h(sacc[n1f], qal, kbh1);
            }
        }
        __syncthreads();   // all warps done reading K smem

        // prefetch next K while softmax+PV run
        if (kt + 1 < kt1) {
            const int kn = (kt + 1) << 6;
            for (int u = tid; u < 1024; u += 128) {
                const int r = u >> 4, c = u & 15;
                cp16(sKh + r * FQSTR + c * 16,
                     qh + koff + (size_t)(kn + r) * QKV3 + c * 8);
            }
            CP_COMMIT();
        }

        // scale + mask + online softmax
        float mt0 = -1e30f, mt1 = -1e30f;
#pragma unroll
        for (int nf = 0; nf < 8; nf++) {
#pragma unroll
            for (int e = 0; e < 4; e++) {
                float v = sacc[nf][e] * SCALE;
                if (win) {
                    const int col = k0 + nf * 8 + 2 * t + (e & 1);
                    const int row = row0 + (e >> 1) * 8;
                    const int dq = row - col;
                    if (dq > HWIN || dq < -HWIN) v = -1e30f;
                }
                sacc[nf][e] = v;
            }
            mt0 = fmaxf(mt0, fmaxf(sacc[nf][0], sacc[nf][1]));
            mt1 = fmaxf(mt1, fmaxf(sacc[nf][2], sacc[nf][3]));
        }
        mt0 = fmaxf(mt0, __shfl_xor_sync(0xffffffffu, mt0, 1));
        mt0 = fmaxf(mt0, __shfl_xor_sync(0xffffffffu, mt0, 2));
        mt1 = fmaxf(mt1, __shfl_xor_sync(0xffffffffu, mt1, 1));
        mt1 = fmaxf(mt1, __shfl_xor_sync(0xffffffffu, mt1, 2));
        const float mn0 = fmaxf(m0, mt0), mn1 = fmaxf(m1, mt1);
        const float al0 = __expf(m0 - mn0), al1 = __expf(m1 - mn1);
        m0 = mn0; m1 = mn1;
        l0 *= al0; l1 *= al1;
#pragma unroll
        for (int dn = 0; dn < 16; dn++) {
            oacc[dn][0] *= al0; oacc[dn][1] *= al0;
            oacc[dn][2] *= al1; oacc[dn][3] *= al1;
        }

        // P = exp(S - m), fp16 hi/lo split in registers
        uint32_t pah[4][4], pal[4][4];
#pragma unroll
        for (int c = 0; c < 4; c++) {
            float p0 = __expf(sacc[2 * c][0] - mn0);
            float p1 = __expf(sacc[2 * c][1] - mn0);
            float p2 = __expf(sacc[2 * c][2] - mn1);
            float p3 = __expf(sacc[2 * c][3] - mn1);
            float r0 = __expf(sacc[2 * c + 1][0] - mn0);
            float r1 = __expf(sacc[2 * c + 1][1] - mn0);
            float r2 = __expf(sacc[2 * c + 1][2] - mn1);
            float r3 = __expf(sacc[2 * c + 1][3] - mn1);
            l0 += p0 + p1 + r0 + r1;
            l1 += p2 + p3 + r2 + r3;
            pah[c][0] = packh(p0, p1);
            pah[c][1] = packh(p2, p3);
            pah[c][2] = packh(r0, r1);
            pah[c][3] = packh(r2, r3);
            pal[c][0] = packh(p0 - h2f(p0), p1 - h2f(p1));
            pal[c][1] = packh(p2 - h2f(p2), p3 - h2f(p3));
            pal[c][2] = packh(r0 - h2f(r0), r1 - h2f(r1));
            pal[c][3] = packh(r2 - h2f(r2), r3 - h2f(r3));
        }

        // O += Ph@Vh + Pl@Vh; V natural, trans ldmatrix
#pragma unroll
        for (int c = 0; c < 4; c++) {
#pragma unroll
            for (int dp = 0; dp < 8; dp++) {
                const int d0 = 2 * dp, d1 = d0 + 1;
                uint32_t vbh0[2], vbh1[2];
                const uint32_t vo0 = (c * 16 + v_row) * FQSTR + d0 * 16;
                const uint32_t vo1 = (c * 16 + v_row) * FQSTR + d1 * 16;
                ldm_x2t(vbh0, sVh + vo0);
                ldm_x2t(vbh1, sVh + vo1);
                mma16816h(oacc[d0], pah[c], vbh0);
                mma16816h(oacc[d1], pah[c], vbh1);
                mma16816h(oacc[d0], pal[c], vbh0);
                mma16816h(oacc[d1], pal[c], vbh1);
            }
        }
        __syncthreads();   // all warps done reading V smem

        if (kt + 1 < kt1) {
            const int kn = (kt + 1) << 6;
            for (int u = tid; u < 1024; u += 128) {
                const int r = u >> 4, c = u & 15;
                cp16(sVh + r * FQSTR + c * 16,
                     qh + voff + (size_t)(kn + r) * QKV3 + c * 8);
            }
            CP_COMMIT();
        }
    }

    // finalize: reduce l across t-group, normalize, write fp16 (hi only)
    l0 += __shfl_xor_sync(0xffffffffu, l0, 1);
    l0 += __shfl_xor_sync(0xffffffffu, l0, 2);
    l1 += __shfl_xor_sync(0xffffffffu, l1, 1);
    l1 += __shfl_xor_sync(0xffffffffu, l1, 2);
    const float inv0 = 1.f / l0, inv1 = 1.f / l1;

    const size_t ob0 = ((size_t)b * S_ + row0) * D_ + h * HD_;
    const size_t ob1 = ob0 + 8 * D_;
#pragma unroll
    for (int dn = 0; dn < 16; dn++) {
        const int col = dn * 8 + 2 * t;
        *(uint32_t*)(attnh + ob0 + col) =
            packh(oacc[dn][0] * inv0, oacc[dn][1] * inv0);
        *(uint32_t*)(attnh + ob1 + col) =
            packh(oacc[dn][2] * inv1, oacc[dn][3] * inv1);
    }
}

// ---------------------------------------------------------------------------
// Global heads: qkv reconstructed from fp16 hi+lo; writes fp16 attn (hi).
// ---------------------------------------------------------------------------
__global__ __launch_bounds__(256) void global_attn(
    const __half* __restrict__ qh, const __half* __restrict__ ql,
    __half* __restrict__ attnh)
{
    const int wip  = threadIdx.x >> 5;
    const int lane = threadIdx.x & 31;
    const int wid  = blockIdx.x * 8 + wip;
    const int q  = wid & (S_ - 1);
    const int hg = (wid >> 11) & 1;
    const int b  = wid >> 12;
    const int h  = NFULL + NLOCAL + hg;

    const size_t base = (size_t)b * S_ * QKV3 + (size_t)h * HD_;
    const size_t qp  = base + (size_t)q * QKV3;
    const size_t kp0 = base + 1536;
    const size_t kp1 = base + 1536 + (size_t)(S_ - 1) * QKV3;
    const size_t vp0 = base + 3072;
    const size_t vp1 = base + 3072 + (size_t)(S_ - 1) * QKV3;

#define RD(off, d) (__half2float(qh[(off) + (d)]) + __half2float(ql[(off) + (d)]))

    float s0 = 0.f, s1 = 0.f;
#pragma unroll
    for (int c = 0; c < 4; c++) {
        const int d = lane + (c << 5);
        const float qd = RD(qp, d);
        s0 += qd * RD(kp0, d);
        s1 += qd * RD(kp1, d);
    }
#pragma unroll
    for (int o = 16; o > 0; o >>= 1) {
        s0 += __shfl_xor_sync(0xffffffffu, s0, o);
        s1 += __shfl_xor_sync(0xffffffffu, s1, o);
    }
    s0 *= SCALE; s1 *= SCALE;
    const float mx = fmaxf(s0, s1);
    float e0 = __expf(s0 - mx), e1 = __expf(s1 - mx);
    const float inv = 1.f / (e0 + e1);
    e0 *= inv; e1 *= inv;

    const size_t op = ((size_t)b * S_ + q) * D_ + h * HD_;
#pragma unroll
    for (int c = 0; c < 4; c++) {
        const int d = lane + (c << 5);
        attnh[op + d] = __float2half(e0 * RD(vp0, d) + e1 * RD(vp1, d));
    }
#undef RD
}

// ---------------------------------------------------------------------------
extern "C" void kernel_launch(void* const* d_in, const int* in_sizes, int n_in,
                              void* d_out, int out_size)
{
    const float* x    = (const float*)d_in[0];
    const float* Wqkv = (const float*)d_in[1];
    const float* bqkv = (const float*)d_in[2];
    const float* Wout = (const float*)d_in[3];
    const float* bout = (const float*)d_in[4];
    float* out = (float*)d_out;

    __half *qkvh, *qkvl, *X1, *A21, *Wq, *Wo;
    cudaGetSymbolAddress((void**)&qkvh, g_qkvh);
    cudaGetSymbolAddress((void**)&qkvl, g_qkvl);
    cudaGetSymbolAddress((void**)&X1,  g_X1);
    cudaGetSymbolAddress((void**)&A21, g_A21);
    cudaGetSymbolAddress((void**)&Wq,  g_Wq);
    cudaGetSymbolAddress((void**)&Wo,  g_Wo);

    cudaFuncSetAttribute(gemm1h,
                         cudaFuncAttributeMaxDynamicSharedMemorySize, GEMM1_SMEM);
    cudaFuncSetAttribute(flash_mma,
                         cudaFuncAttributeMaxDynamicSharedMemorySize, FL_SMEM);

    // Input/weight conversions (all single-term fp16)
    k_cvt_h1<<<(MROWS * KDIM) / 1024, 256>>>(x, X1, MROWS * KDIM);
    k_splitT_h1<<<dim3(QKV3 / 32, KDIM / 32), 256>>>(Wqkv, Wq, KDIM, QKV3);
    k_splitT_h1<<<dim3(D_ / 32, KDIM / 32), 256>>>(Wout, Wo, KDIM, D_);

    // 1) QKV projection (fp16 1-term) -> qkv fp16 hi/lo; dead tiles skipped
    gemm1h<<<dim3(32, MROWS / 128), 256, GEMM1_SMEM>>>(
        X1, Wq, bqkv, nullptr, qkvh, qkvl, QKV3, 1);
    fix_globalqkv<<<16, 128>>>(x, Wqkv, bqkv, qkvh, qkvl);

    // 2) Attention (full + windowed fused) + global heads -> fp16 attn
    flash_mma<<<dim3(S_ / 64, B_ * (NFULL + NLOCAL)), 128, FL_SMEM>>>(
        qkvh, qkvl, A21);
    global_attn<<<(B_ * 2 * S_) / 8, 256>>>(qkvh, qkvl, A21);

    // 3) Output projection (fp16 1-term) -> fp32 final
    gemm1h<<<dim3(D_ / 128, MROWS / 128), 256, GEMM1_SMEM>>>(
        A21, Wo, bout, out, nullptr, nullptr, D_, 0);
}

// round 16
// speedup vs baseline: 2.0840x; 1.0903x over previous
#include <cuda_runtime.h>
#include <cuda_bf16.h>
#include <cuda_fp16.h>
#include <stdint.h>
#include <math.h>

#define B_    2
#define S_    2048
#define D_    1536
#define QKV3  4608
#define HD_   128
#define NFULL 6
#define NLOCAL 4
#define HWIN  32
#define SCALE 0.08838834764831845f   // 1/sqrt(128)
#define KDIM  1536
#define MROWS 4096                   // B_*S_

// ---------------------------------------------------------------------------
// Scratch (device globals: allocation-free)
// ---------------------------------------------------------------------------
__device__ __half g_qkvh[(size_t)MROWS * QKV3];   // qkv hi (fp16)
__device__ __half g_qkvl[(size_t)MROWS * QKV3];   // qkv lo (fp16, for flash Q)
__device__ __half g_X1[(size_t)MROWS * KDIM];     // x, fp16 1-term
__device__ __half g_A21[(size_t)MROWS * KDIM];    // attn out, fp16 1-term
__device__ __half g_Wq[(size_t)QKV3 * KDIM];      // weights 1-term [N][K]
__device__ __half g_Wo[(size_t)D_ * KDIM];

// ---------------------------------------------------------------------------
// PTX helpers (sm_80-baseline: legal on plain compute_103 target)
// ---------------------------------------------------------------------------
__device__ __forceinline__ uint32_t smem_u32(const void* p) {
    uint32_t a;
    asm("{ .reg .u64 t; cvta.to.shared.u64 t, %1; cvt.u32.u64 %0, t; }"
        : "=r"(a) : "l"(p));
    return a;
}
__device__ __forceinline__ void cp16(uint32_t d, const void* s) {
    asm volatile("cp.async.cg.shared.global [%0], [%1], 16;" :: "r"(d), "l"(s));
}
#define CP_COMMIT() asm volatile("cp.async.commit_group;" ::: "memory")

__device__ __forceinline__ void ldm_x4(uint32_t* r, uint32_t addr) {
    asm volatile("ldmatrix.sync.aligned.m8n8.x4.shared.b16 {%0,%1,%2,%3}, [%4];"
                 : "=r"(r[0]), "=r"(r[1]), "=r"(r[2]), "=r"(r[3]) : "r"(addr));
}
__device__ __forceinline__ void ldm_x2(uint32_t* r, uint32_t addr) {
    asm volatile("ldmatrix.sync.aligned.m8n8.x2.shared.b16 {%0,%1}, [%2];"
                 : "=r"(r[0]), "=r"(r[1]) : "r"(addr));
}
__device__ __forceinline__ void ldm_x2t(uint32_t* r, uint32_t addr) {
    asm volatile("ldmatrix.sync.aligned.m8n8.x2.trans.shared.b16 {%0,%1}, [%2];"
                 : "=r"(r[0]), "=r"(r[1]) : "r"(addr));
}
// fp16 mma, fp32 accum
__device__ __forceinline__ void mma16816h(float* c, const uint32_t* a,
                                          const uint32_t* b) {
    asm volatile(
        "mma.sync.aligned.m16n8k16.row.col.f32.f16.f16.f32 "
        "{%0,%1,%2,%3}, {%4,%5,%6,%7}, {%8,%9}, {%0,%1,%2,%3};"
        : "+f"(c[0]), "+f"(c[1]), "+f"(c[2]), "+f"(c[3])
        : "r"(a[0]), "r"(a[1]), "r"(a[2]), "r"(a[3]), "r"(b[0]), "r"(b[1]));
}
// pack two f32 -> f16x2 (first arg -> low half / lower address)
__device__ __forceinline__ uint32_t packh(float lo, float hi) {
    uint32_t r;
    asm("cvt.rn.f16x2.f32 %0, %1, %2;" : "=r"(r) : "f"(hi), "f"(lo));
    return r;
}
__device__ __forceinline__ float h2f(float p) {
    return __half2float(__float2half(p));
}

// ---------------------------------------------------------------------------
// Conversion kernels
// ---------------------------------------------------------------------------
// fp32 -> fp16 (single term)
__global__ __launch_bounds__(256) void k_cvt_h1(
    const float* __restrict__ in, __half* __restrict__ hi, int n)
{
    int i = (blockIdx.x * 256 + threadIdx.x) * 4;
    if (i >= n) return;
    float4 v = *(const float4*)(in + i);
    uint32_t* hp = (uint32_t*)(hi + i);
    hp[0] = packh(v.x, v.y);
    hp[1] = packh(v.z, v.w);
}

// fp32 [K,N] -> fp16 [N,K] single-term transposed
__global__ __launch_bounds__(256) void k_splitT_h1(
    const float* __restrict__ in, __half* __restrict__ hi, int Kd, int Nd)
{
    __shared__ float t[32][33];
    const int n0 = blockIdx.x * 32, k0 = blockIdx.y * 32;
    const int tx = threadIdx.x & 31, ty = threadIdx.x >> 5;
#pragma unroll
    for (int j = 0; j < 32; j += 8)
        t[ty + j][tx] = in[(size_t)(k0 + ty + j) * Nd + n0 + tx];
    __syncthreads();
#pragma unroll
    for (int j = 0; j < 32; j += 8)
        hi[(size_t)(n0 + ty + j) * Kd + k0 + tx] = __float2half(t[tx][ty + j]);
}

// ---------------------------------------------------------------------------
// Fixup: exact fp32 dot products for the 4 skipped global-head K/V column
// tiles at the only 4 rows global_attn reads.
// ---------------------------------------------------------------------------
__global__ __launch_bounds__(128) void fix_globalqkv(
    const float* __restrict__ x, const float* __restrict__ Wqkv,
    const float* __restrict__ bqkv,
    __half* __restrict__ qkvh, __half* __restrict__ qkvl)
{
    __shared__ float xs[KDIM];
    const int rows[4] = {0, S_ - 1, S_, 2 * S_ - 1};
    const int cols[4] = {2816, 2944, 4352, 4480};
    const int row = rows[blockIdx.x >> 2];
    const int c   = cols[blockIdx.x & 3] + threadIdx.x;

    for (int k = threadIdx.x; k < KDIM; k += 128)
        xs[k] = x[(size_t)row * KDIM + k];
    __syncthreads();

    float s = 0.f;
#pragma unroll 8
    for (int k = 0; k < KDIM; k++)
        s += xs[k] * Wqkv[(size_t)k * QKV3 + c];
    s += bqkv[c];

    const size_t o = (size_t)row * QKV3 + c;
    const __half h = __float2half(s);
    qkvh[o] = h;
    qkvl[o] = __float2half(s - __half2float(h));
}

// ---------------------------------------------------------------------------
// FP16 1-term GEMM: acc = A@B^T + bias.
// A: [M][K] fp16. B: [N][K] fp16. 128x128 tile, BK=32, 8 warps (2x4),
// 3-stage cp.async, 2 CTAs/SM (smem 61.4 KB/CTA).
// mode 0: write fp32 C. mode 1: write fp16 hi/lo (Ch, Cl) and remap
// blockIdx.x to skip the 4 dead global-head column tiles {22,23,34,35}.
// ---------------------------------------------------------------------------
#define NCH    (KDIM / 32)          // 48
#define AROWB  80
#define TILEB  (128 * AROWB)        // 10240
#define STAGE1 (2 * TILEB)          // 20480
#define GEMM1_SMEM (3 * STAGE1)     // 61440

__global__ __launch_bounds__(256, 2) void gemm1h(
    const __half* __restrict__ Ag, const __half* __restrict__ Bg,
    const float* __restrict__ bias, float* __restrict__ C,
    __half* __restrict__ Ch, __half* __restrict__ Cl,
    int Ncols, int mode)
{
    extern __shared__ char smem[];
    const uint32_t sb = smem_u32(smem);
    const int tid  = threadIdx.x;
    const int wid  = tid >> 5;
    const int lane = tid & 31;
    const int warp_m = wid & 1;
    const int warp_n = wid >> 1;
    const int m0 = blockIdx.y * 128;
    int bx = blockIdx.x;
    if (mode == 1 && bx >= 22) bx += 2;   // skip dead tiles 22,23 (34,35 off-grid)
    const int n0 = bx * 128;

    const char* gA = (const char*)(Ag + (size_t)m0 * KDIM);
    const char* gB = (const char*)(Bg + (size_t)n0 * KDIM);

    float acc[4][4][4];
#pragma unroll
    for (int i = 0; i < 4; i++)
#pragma unroll
        for (int j = 0; j < 4; j++)
#pragma unroll
            for (int k = 0; k < 4; k++) acc[i][j][k] = 0.f;

#define LOAD_CHUNK1(ch, stage) do {                                            \
        const uint32_t st = sb + (stage) * STAGE1;                             \
        const size_t kb = (size_t)(ch) * 64;                                   \
        _Pragma("unroll")                                                      \
        for (int t = 0; t < 4; t++) {                                          \
            const int u = tid + t * 256;                                       \
            const int tile = u >> 9;                                           \
            const int r = (u >> 2) & 127;                                      \
            const int c = u & 3;                                               \
            const char* g = (tile == 0) ? gA : gB;                             \
            cp16(st + tile * TILEB + r * AROWB + c * 16,                       \
                 g + (size_t)r * (KDIM * 2) + kb + c * 16);                    \
        }                                                                      \
        CP_COMMIT();                                                           \
    } while (0)

    LOAD_CHUNK1(0, 0);
    LOAD_CHUNK1(1, 1);
    LOAD_CHUNK1(2, 2);

    const int a_row  = warp_m * 64 + (lane & 15);
    const int a_koff = (lane >> 4) * 16;
    const int b_row  = warp_n * 32 + (lane & 7);
    const int b_koff = ((lane >> 3) & 1) * 16;

    for (int i = 0; i < NCH; i++) {
        const int p = i % 3;
        if (i + 1 < NCH) asm volatile("cp.async.wait_group 2;" ::: "memory");
        else             asm volatile("cp.async.wait_group 0;" ::: "memory");
        __syncthreads();

        const uint32_t sA = sb + p * STAGE1;
        const uint32_t sB = sA + TILEB;

#pragma unroll
        for (int kk = 0; kk < 2; kk++) {
            uint32_t bh[4][2];
#pragma unroll
            for (int nf = 0; nf < 4; nf++) {
                const uint32_t off = (b_row + nf * 8) * AROWB + kk * 32 + b_koff;
                ldm_x2(bh[nf], sB + off);
            }
#pragma unroll
            for (int mf = 0; mf < 4; mf++) {
                uint32_t ah[4];
                const uint32_t off = (a_row + mf * 16) * AROWB + kk * 32 + a_koff;
                ldm_x4(ah, sA + off);
#pragma unroll
                for (int nf = 0; nf < 4; nf++) mma16816h(acc[mf][nf], ah, bh[nf]);
            }
        }
        __syncthreads();
        if (i + 3 < NCH) LOAD_CHUNK1(i + 3, p);
        else CP_COMMIT();
    }

    const int g_  = lane >> 2;
    const int tg  = lane & 3;
#pragma unroll
    for (int mf = 0; mf < 4; mf++) {
        const int row = m0 + warp_m * 64 + mf * 16 + g_;
#pragma unroll
        for (int nf = 0; nf < 4; nf++) {
            const int col = n0 + warp_n * 32 + nf * 8 + tg * 2;
            const float b0 = bias[col], b1 = bias[col + 1];
            const float v00 = acc[mf][nf][0] + b0, v01 = acc[mf][nf][1] + b1;
            const float v10 = acc[mf][nf][2] + b0, v11 = acc[mf][nf][3] + b1;
            if (mode == 0) {
                *(float2*)(C + (size_t)row * Ncols + col) = make_float2(v00, v01);
                *(float2*)(C + (size_t)(row + 8) * Ncols + col) = make_float2(v10, v11);
            } else {
                const size_t o0 = (size_t)row * Ncols + col;
                const size_t o1 = (size_t)(row + 8) * Ncols + col;
                *(uint32_t*)(Ch + o0) = packh(v00, v01);
                *(uint32_t*)(Ch + o1) = packh(v10, v11);
                *(uint32_t*)(Cl + o0) = packh(v00 - h2f(v00), v01 - h2f(v01));
                *(uint32_t*)(Cl + o1) = packh(v10 - h2f(v10), v11 - h2f(v11));
            }
        }
    }
}

// ---------------------------------------------------------------------------
// Flash attention, fp16: S = Qh@Kh + Ql@Kh (2-term Q), O = Ph@Vh (1-term P).
// Mq=64, Nk=64, hd=128. V natural + ldmatrix.trans. Smem: Qh,Ql,Kh,Vh.
// K/V prefetched intra-tile via cp.async. Writes fp16 attn (hi only).
// ---------------------------------------------------------------------------
#define FQSTR 272                 // row stride bytes (128 fp16 + 8 pad)
#define FQB   (64 * FQSTR)        // 17408
#define FL_SMEM (4 * FQB)         // 69632

__global__ __launch_bounds__(128) void flash_mma(
    const __half* __restrict__ qh, const __half* __restrict__ ql,
    __half* __restrict__ attnh)
{
    extern __shared__ char smem[];
    const uint32_t sb  = smem_u32(smem);
    const uint32_t sQh = sb,            sQl = sb + FQB;
    const uint32_t sKh = sb + 2 * FQB,  sVh = sb + 3 * FQB;

    const int tid = threadIdx.x, wid = tid >> 5, lane = tid & 31;
    const int g = lane >> 2, t = lane & 3;

    int yy = blockIdx.y, b, h, win;
    if (yy < B_ * NFULL) { b = yy / NFULL;  h = yy % NFULL;          win = 0; }
    else { yy -= B_ * NFULL; b = yy / NLOCAL; h = NFULL + yy % NLOCAL; win = 1; }
    const int q0 = blockIdx.x * 64;

    const size_t rb   = (size_t)b * S_ * QKV3 + (size_t)h * HD_;
    const size_t koff = rb + 1536;
    const size_t voff = rb + 3072;

    int kt0 = 0, kt1 = S_ >> 6;
    if (win) {
        kt0 = (q0 >= HWIN) ? ((q0 - HWIN) >> 6) : 0;
        kt1 = min(kt1, ((q0 + 63 + HWIN) >> 6) + 1);
    }

    // Q tiles (hi+lo, once) + first K/V hi tiles
    for (int u = tid; u < 1024; u += 128) {
        const int r = u >> 4, c = u & 15;
        const size_t go = rb + (size_t)(q0 + r) * QKV3 + c * 8;
        cp16(sQh + r * FQSTR + c * 16, qh + go);
        cp16(sQl + r * FQSTR + c * 16, ql + go);
    }
    {
        const int k0 = kt0 << 6;
        for (int u = tid; u < 1024; u += 128) {
            const int r = u >> 4, c = u & 15;
            cp16(sKh + r * FQSTR + c * 16, qh + koff + (size_t)(k0 + r) * QKV3 + c * 8);
            cp16(sVh + r * FQSTR + c * 16, qh + voff + (size_t)(k0 + r) * QKV3 + c * 8);
        }
    }
    CP_COMMIT();

    float oacc[16][4];
#pragma unroll
    for (int i = 0; i < 16; i++)
#pragma unroll
        for (int j = 0; j < 4; j++) oacc[i][j] = 0.f;
    float m0 = -1e30f, m1 = -1e30f, l0 = 0.f, l1 = 0.f;

    const int a_row  = wid * 16 + (lane & 15);
    const int a_koff = (lane >> 4) * 16;
    const int b_r    = lane & 7;
    const int b_koff = ((lane >> 3) & 1) * 16;
    const int v_row  = lane & 15;          // trans ldmatrix row (key)
    const int row0   = q0 + wid * 16 + g;

    for (int kt = kt0; kt < kt1; kt++) {
        const int k0 = kt << 6;
        asm volatile("cp.async.wait_group 0;" ::: "memory");
        __syncthreads();

        // S = Qh@Kh + Ql@Kh
        float sacc[8][4];
#pragma unroll
        for (int i = 0; i < 8; i++)
#pragma unroll
            for (int j = 0; j < 4; j++) sacc[i][j] = 0.f;
#pragma unroll
        for (int kc = 0; kc < 8; kc++) {
            uint32_t qah[4], qal[4];
            const uint32_t aoff = a_row * FQSTR + kc * 32 + a_koff;
            ldm_x4(qah, sQh + aoff);
            ldm_x4(qal, sQl + aoff);
#pragma unroll
            for (int np = 0; np < 4; np++) {
                const int n0f = 2 * np, n1f = n0f + 1;
                uint32_t kbh0[2], kbh1[2];
                const uint32_t bo0 = (n0f * 8 + b_r) * FQSTR + kc * 32 + b_koff;
                const uint32_t bo1 = (n1f * 8 + b_r) * FQSTR + kc * 32 + b_koff;
                ldm_x2(kbh0, sKh + bo0);
                ldm_x2(kbh1, sKh + bo1);
                mma16816h(sacc[n0f], qah, kbh0);
                mma16816h(sacc[n1f], qah, kbh1);
                mma16816h(sacc[n0f], qal, kbh0);
                mma16816h(sacc[n1f], qal, kbh1);
            }
        }
        __syncthreads();   // all warps done reading K smem

        // prefetch next K while softmax+PV run
        if (kt + 1 < kt1) {
            const int kn = (kt + 1) << 6;
            for (int u = tid; u < 1024; u += 128) {
                const int r = u >> 4, c = u & 15;
                cp16(sKh + r * FQSTR + c * 16,
                     qh + koff + (size_t)(kn + r) * QKV3 + c * 8);
            }
            CP_COMMIT();
        }

        // scale + mask + online softmax
        float mt0 = -1e30f, mt1 = -1e30f;
#pragma unroll
        for (int nf = 0; nf < 8; nf++) {
#pragma unroll
            for (int e = 0; e < 4; e++) {
                float v = sacc[nf][e] * SCALE;
                if (win) {
                    const int col = k0 + nf * 8 + 2 * t + (e & 1);
                    const int row = row0 + (e >> 1) * 8;
                    const int dq = row - col;
                    if (dq > HWIN || dq < -HWIN) v = -1e30f;
                }
                sacc[nf][e] = v;
            }
            mt0 = fmaxf(mt0, fmaxf(sacc[nf][0], sacc[nf][1]));
            mt1 = fmaxf(mt1, fmaxf(sacc[nf][2], sacc[nf][3]));
        }
        mt0 = fmaxf(mt0, __shfl_xor_sync(0xffffffffu, mt0, 1));
        mt0 = fmaxf(mt0, __shfl_xor_sync(0xffffffffu, mt0, 2));
        mt1 = fmaxf(mt1, __shfl_xor_sync(0xffffffffu, mt1, 1));
        mt1 = fmaxf(mt1, __shfl_xor_sync(0xffffffffu, mt1, 2));
        const float mn0 = fmaxf(m0, mt0), mn1 = fmaxf(m1, mt1);
        const float al0 = __expf(m0 - mn0), al1 = __expf(m1 - mn1);
        m0 = mn0; m1 = mn1;
        l0 *= al0; l1 *= al1;
#pragma unroll
        for (int dn = 0; dn < 16; dn++) {
            oacc[dn][0] *= al0; oacc[dn][1] *= al0;
            oacc[dn][2] *= al1; oacc[dn][3] *= al1;
        }

        // P = exp(S - m), fp16 (hi only) in registers
        uint32_t pah[4][4];
#pragma unroll
        for (int c = 0; c < 4; c++) {
            float p0 = __expf(sacc[2 * c][0] - mn0);
            float p1 = __expf(sacc[2 * c][1] - mn0);
            float p2 = __expf(sacc[2 * c][2] - mn1);
            float p3 = __expf(sacc[2 * c][3] - mn1);
            float r0 = __expf(sacc[2 * c + 1][0] - mn0);
            float r1 = __expf(sacc[2 * c + 1][1] - mn0);
            float r2 = __expf(sacc[2 * c + 1][2] - mn1);
            float r3 = __expf(sacc[2 * c + 1][3] - mn1);
            l0 += p0 + p1 + r0 + r1;
            l1 += p2 + p3 + r2 + r3;
            pah[c][0] = packh(p0, p1);
            pah[c][1] = packh(p2, p3);
            pah[c][2] = packh(r0, r1);
            pah[c][3] = packh(r2, r3);
        }

        // O += Ph@Vh; V natural, trans ldmatrix
#pragma unroll
        for (int c = 0; c < 4; c++) {
#pragma unroll
            for (int dp = 0; dp < 8; dp++) {
                const int d0 = 2 * dp, d1 = d0 + 1;
                uint32_t vbh0[2], vbh1[2];
                const uint32_t vo0 = (c * 16 + v_row) * FQSTR + d0 * 16;
                const uint32_t vo1 = (c * 16 + v_row) * FQSTR + d1 * 16;
                ldm_x2t(vbh0, sVh + vo0);
                ldm_x2t(vbh1, sVh + vo1);
                mma16816h(oacc[d0], pah[c], vbh0);
                mma16816h(oacc[d1], pah[c], vbh1);
            }
        }
        __syncthreads();   // all warps done reading V smem

        if (kt + 1 < kt1) {
            const int kn = (kt + 1) << 6;
            for (int u = tid; u < 1024; u += 128) {
                const int r = u >> 4, c = u & 15;
                cp16(sVh + r * FQSTR + c * 16,
                     qh + voff + (size_t)(kn + r) * QKV3 + c * 8);
            }
            CP_COMMIT();
        }
    }

    // finalize: reduce l across t-group, normalize, write fp16 (hi only)
    l0 += __shfl_xor_sync(0xffffffffu, l0, 1);
    l0 += __shfl_xor_sync(0xffffffffu, l0, 2);
    l1 += __shfl_xor_sync(0xffffffffu, l1, 1);
    l1 += __shfl_xor_sync(0xffffffffu, l1, 2);
    const float inv0 = 1.f / l0, inv1 = 1.f / l1;

    const size_t ob0 = ((size_t)b * S_ + row0) * D_ + h * HD_;
    const size_t ob1 = ob0 + 8 * D_;
#pragma unroll
    for (int dn = 0; dn < 16; dn++) {
        const int col = dn * 8 + 2 * t;
        *(uint32_t*)(attnh + ob0 + col) =
            packh(oacc[dn][0] * inv0, oacc[dn][1] * inv0);
        *(uint32_t*)(attnh + ob1 + col) =
            packh(oacc[dn][2] * inv1, oacc[dn][3] * inv1);
    }
}

// ---------------------------------------------------------------------------
// Global heads: qkv reconstructed from fp16 hi+lo; writes fp16 attn (hi).
// ---------------------------------------------------------------------------
__global__ __launch_bounds__(256) void global_attn(
    const __half* __restrict__ qh, const __half* __restrict__ ql,
    __half* __restrict__ attnh)
{
    const int wip  = threadIdx.x >> 5;
    const int lane = threadIdx.x & 31;
    const int wid  = blockIdx.x * 8 + wip;
    const int q  = wid & (S_ - 1);
    const int hg = (wid >> 11) & 1;
    const int b  = wid >> 12;
    const int h  = NFULL + NLOCAL + hg;

    const size_t base = (size_t)b * S_ * QKV3 + (size_t)h * HD_;
    const size_t qp  = base + (size_t)q * QKV3;
    const size_t kp0 = base + 1536;
    const size_t kp1 = base + 1536 + (size_t)(S_ - 1) * QKV3;
    const size_t vp0 = base + 3072;
    const size_t vp1 = base + 3072 + (size_t)(S_ - 1) * QKV3;

#define RD(off, d) (__half2float(qh[(off) + (d)]) + __half2float(ql[(off) + (d)]))

    float s0 = 0.f, s1 = 0.f;
#pragma unroll
    for (int c = 0; c < 4; c++) {
        const int d = lane + (c << 5);
        const float qd = RD(qp, d);
        s0 += qd * RD(kp0, d);
        s1 += qd * RD(kp1, d);
    }
#pragma unroll
    for (int o = 16; o > 0; o >>= 1) {
        s0 += __shfl_xor_sync(0xffffffffu, s0, o);
        s1 += __shfl_xor_sync(0xffffffffu, s1, o);
    }
    s0 *= SCALE; s1 *= SCALE;
    const float mx = fmaxf(s0, s1);
    float e0 = __expf(s0 - mx), e1 = __expf(s1 - mx);
    const float inv = 1.f / (e0 + e1);
    e0 *= inv; e1 *= inv;

    const size_t op = ((size_t)b * S_ + q) * D_ + h * HD_;
#pragma unroll
    for (int c = 0; c < 4; c++) {
        const int d = lane + (c << 5);
        attnh[op + d] = __float2half(e0 * RD(vp0, d) + e1 * RD(vp1, d));
    }
#undef RD
}

// ---------------------------------------------------------------------------
extern "C" void kernel_launch(void* const* d_in, const int* in_sizes, int n_in,
                              void* d_out, int out_size)
{
    const float* x    = (const float*)d_in[0];
    const float* Wqkv = (const float*)d_in[1];
    const float* bqkv = (const float*)d_in[2];
    const float* Wout = (const float*)d_in[3];
    const float* bout = (const float*)d_in[4];
    float* out = (float*)d_out;

    __half *qkvh, *qkvl, *X1, *A21, *Wq, *Wo;
    cudaGetSymbolAddress((void**)&qkvh, g_qkvh);
    cudaGetSymbolAddress((void**)&qkvl, g_qkvl);
    cudaGetSymbolAddress((void**)&X1,  g_X1);
    cudaGetSymbolAddress((void**)&A21, g_A21);
    cudaGetSymbolAddress((void**)&Wq,  g_Wq);
    cudaGetSymbolAddress((void**)&Wo,  g_Wo);

    cudaFuncSetAttribute(gemm1h,
                         cudaFuncAttributeMaxDynamicSharedMemorySize, GEMM1_SMEM);
    cudaFuncSetAttribute(flash_mma,
                         cudaFuncAttributeMaxDynamicSharedMemorySize, FL_SMEM);

    // Input/weight conversions (all single-term fp16)
    k_cvt_h1<<<(MROWS * KDIM) / 1024, 256>>>(x, X1, MROWS * KDIM);
    k_splitT_h1<<<dim3(QKV3 / 32, KDIM / 32), 256>>>(Wqkv, Wq, KDIM, QKV3);
    k_splitT_h1<<<dim3(D_ / 32, KDIM / 32), 256>>>(Wout, Wo, KDIM, D_);

    // 1) QKV projection (fp16 1-term) -> qkv fp16 hi/lo; dead tiles skipped
    gemm1h<<<dim3(32, MROWS / 128), 256, GEMM1_SMEM>>>(
        X1, Wq, bqkv, nullptr, qkvh, qkvl, QKV3, 1);
    fix_globalqkv<<<16, 128>>>(x, Wqkv, bqkv, qkvh, qkvl);

    // 2) Attention (full + windowed fused) + global heads -> fp16 attn
    flash_mma<<<dim3(S_ / 64, B_ * (NFULL + NLOCAL)), 128, FL_SMEM>>>(
        qkvh, qkvl, A21);
    global_attn<<<(B_ * 2 * S_) / 8, 256>>>(qkvh, qkvl, A21);

    // 3) Output projection (fp16 1-term) -> fp32 final
    gemm1h<<<dim3(D_ / 128, MROWS / 128), 256, GEMM1_SMEM>>>(
        A21, Wo, bout, out, nullptr, nullptr, D_, 0);
}

// round 17
// speedup vs baseline: 2.3230x; 1.1147x over previous
#include <cuda_runtime.h>
#include <cuda_bf16.h>
#include <cuda_fp16.h>
#include <stdint.h>
#include <math.h>

#define B_    2
#define S_    2048
#define D_    1536
#define QKV3  4608
#define HD_   128
#define NFULL 6
#define NLOCAL 4
#define HWIN  32
#define SCALE 0.08838834764831845f   // 1/sqrt(128)
#define KDIM  1536
#define MROWS 4096                   // B_*S_

// ---------------------------------------------------------------------------
// Scratch (device globals: allocation-free)
// ---------------------------------------------------------------------------
__device__ __half g_qkvh[(size_t)MROWS * QKV3];   // qkv (fp16, 1-term)
__device__ __half g_X1[(size_t)MROWS * KDIM];     // x, fp16 1-term
__device__ __half g_A21[(size_t)MROWS * KDIM];    // attn out, fp16 1-term
__device__ __half g_Wq[(size_t)QKV3 * KDIM];      // weights 1-term [N][K]
__device__ __half g_Wo[(size_t)D_ * KDIM];

// ---------------------------------------------------------------------------
// PTX helpers (sm_80-baseline: legal on plain compute_103 target)
// ---------------------------------------------------------------------------
__device__ __forceinline__ uint32_t smem_u32(const void* p) {
    uint32_t a;
    asm("{ .reg .u64 t; cvta.to.shared.u64 t, %1; cvt.u32.u64 %0, t; }"
        : "=r"(a) : "l"(p));
    return a;
}
__device__ __forceinline__ void cp16(uint32_t d, const void* s) {
    asm volatile("cp.async.cg.shared.global [%0], [%1], 16;" :: "r"(d), "l"(s));
}
#define CP_COMMIT() asm volatile("cp.async.commit_group;" ::: "memory")

__device__ __forceinline__ void ldm_x4(uint32_t* r, uint32_t addr) {
    asm volatile("ldmatrix.sync.aligned.m8n8.x4.shared.b16 {%0,%1,%2,%3}, [%4];"
                 : "=r"(r[0]), "=r"(r[1]), "=r"(r[2]), "=r"(r[3]) : "r"(addr));
}
__device__ __forceinline__ void ldm_x2(uint32_t* r, uint32_t addr) {
    asm volatile("ldmatrix.sync.aligned.m8n8.x2.shared.b16 {%0,%1}, [%2];"
                 : "=r"(r[0]), "=r"(r[1]) : "r"(addr));
}
__device__ __forceinline__ void ldm_x2t(uint32_t* r, uint32_t addr) {
    asm volatile("ldmatrix.sync.aligned.m8n8.x2.trans.shared.b16 {%0,%1}, [%2];"
                 : "=r"(r[0]), "=r"(r[1]) : "r"(addr));
}
// fp16 mma, fp32 accum
__device__ __forceinline__ void mma16816h(float* c, const uint32_t* a,
                                          const uint32_t* b) {
    asm volatile(
        "mma.sync.aligned.m16n8k16.row.col.f32.f16.f16.f32 "
        "{%0,%1,%2,%3}, {%4,%5,%6,%7}, {%8,%9}, {%0,%1,%2,%3};"
        : "+f"(c[0]), "+f"(c[1]), "+f"(c[2]), "+f"(c[3])
        : "r"(a[0]), "r"(a[1]), "r"(a[2]), "r"(a[3]), "r"(b[0]), "r"(b[1]));
}
// pack two f32 -> f16x2 (first arg -> low half / lower address)
__device__ __forceinline__ uint32_t packh(float lo, float hi) {
    uint32_t r;
    asm("cvt.rn.f16x2.f32 %0, %1, %2;" : "=r"(r) : "f"(hi), "f"(lo));
    return r;
}

// ---------------------------------------------------------------------------
// Conversion kernels
// ---------------------------------------------------------------------------
// fp32 -> fp16 (single term)
__global__ __launch_bounds__(256) void k_cvt_h1(
    const float* __restrict__ in, __half* __restrict__ hi, int n)
{
    int i = (blockIdx.x * 256 + threadIdx.x) * 4;
    if (i >= n) return;
    float4 v = *(const float4*)(in + i);
    uint32_t* hp = (uint32_t*)(hi + i);
    hp[0] = packh(v.x, v.y);
    hp[1] = packh(v.z, v.w);
}

// fp32 [K,N] -> fp16 [N,K] single-term transposed
__global__ __launch_bounds__(256) void k_splitT_h1(
    const float* __restrict__ in, __half* __restrict__ hi, int Kd, int Nd)
{
    __shared__ float t[32][33];
    const int n0 = blockIdx.x * 32, k0 = blockIdx.y * 32;
    const int tx = threadIdx.x & 31, ty = threadIdx.x >> 5;
#pragma unroll
    for (int j = 0; j < 32; j += 8)
        t[ty + j][tx] = in[(size_t)(k0 + ty + j) * Nd + n0 + tx];
    __syncthreads();
#pragma unroll
    for (int j = 0; j < 32; j += 8)
        hi[(size_t)(n0 + ty + j) * Kd + k0 + tx] = __float2half(t[tx][ty + j]);
}

// ---------------------------------------------------------------------------
// Fixup: exact fp32 dot products for the 4 skipped global-head K/V column
// tiles at the only 4 rows global_attn reads.
// ---------------------------------------------------------------------------
__global__ __launch_bounds__(128) void fix_globalqkv(
    const float* __restrict__ x, const float* __restrict__ Wqkv,
    const float* __restrict__ bqkv, __half* __restrict__ qkvh)
{
    __shared__ float xs[KDIM];
    const int rows[4] = {0, S_ - 1, S_, 2 * S_ - 1};
    const int cols[4] = {2816, 2944, 4352, 4480};
    const int row = rows[blockIdx.x >> 2];
    const int c   = cols[blockIdx.x & 3] + threadIdx.x;

    for (int k = threadIdx.x; k < KDIM; k += 128)
        xs[k] = x[(size_t)row * KDIM + k];
    __syncthreads();

    float s = 0.f;
#pragma unroll 8
    for (int k = 0; k < KDIM; k++)
        s += xs[k] * Wqkv[(size_t)k * QKV3 + c];
    s += bqkv[c];

    qkvh[(size_t)row * QKV3 + c] = __float2half(s);
}

// ---------------------------------------------------------------------------
// FP16 1-term GEMM: acc = A@B^T + bias.
// A: [M][K] fp16. B: [N][K] fp16. 128x128 tile, BK=32, 8 warps (2x4),
// 2-stage cp.async, 2 CTAs/SM.
// mode 0: write fp32 C. mode 1: write fp16 (Ch) and remap blockIdx.x to
// skip the 4 dead global-head column tiles {22,23,34,35}.
// ---------------------------------------------------------------------------
#define NCH    (KDIM / 32)          // 48
#define AROWB  80
#define TILEB  (128 * AROWB)        // 10240
#define STAGE1 (2 * TILEB)          // 20480
#define GEMM1_SMEM (2 * STAGE1)     // 40960

__global__ __launch_bounds__(256, 2) void gemm1h(
    const __half* __restrict__ Ag, const __half* __restrict__ Bg,
    const float* __restrict__ bias, float* __restrict__ C,
    __half* __restrict__ Ch, int Ncols, int mode)
{
    extern __shared__ char smem[];
    const uint32_t sb = smem_u32(smem);
    const int tid  = threadIdx.x;
    const int wid  = tid >> 5;
    const int lane = tid & 31;
    const int warp_m = wid & 1;
    const int warp_n = wid >> 1;
    const int m0 = blockIdx.y * 128;
    int bx = blockIdx.x;
    if (mode == 1 && bx >= 22) bx += 2;   // skip dead tiles 22,23 (34,35 off-grid)
    const int n0 = bx * 128;

    const char* gA = (const char*)(Ag + (size_t)m0 * KDIM);
    const char* gB = (const char*)(Bg + (size_t)n0 * KDIM);

    float acc[4][4][4];
#pragma unroll
    for (int i = 0; i < 4; i++)
#pragma unroll
        for (int j = 0; j < 4; j++)
#pragma unroll
            for (int k = 0; k < 4; k++) acc[i][j][k] = 0.f;

#define LOAD_CHUNK1(ch, stage) do {                                            \
        const uint32_t st = sb + (stage) * STAGE1;                             \
        const size_t kb = (size_t)(ch) * 64;                                   \
        _Pragma("unroll")                                                      \
        for (int t = 0; t < 4; t++) {                                          \
            const int u = tid + t * 256;                                       \
            const int tile = u >> 9;                                           \
            const int r = (u >> 2) & 127;                                      \
            const int c = u & 3;                                               \
            const char* g = (tile == 0) ? gA : gB;                             \
            cp16(st + tile * TILEB + r * AROWB + c * 16,                       \
                 g + (size_t)r * (KDIM * 2) + kb + c * 16);                    \
        }                                                                      \
        CP_COMMIT();                                                           \
    } while (0)

    LOAD_CHUNK1(0, 0);
    LOAD_CHUNK1(1, 1);

    const int a_row  = warp_m * 64 + (lane & 15);
    const int a_koff = (lane >> 4) * 16;
    const int b_row  = warp_n * 32 + (lane & 7);
    const int b_koff = ((lane >> 3) & 1) * 16;

    for (int i = 0; i < NCH; i++) {
        const int p = i & 1;
        if (i + 1 < NCH) asm volatile("cp.async.wait_group 1;" ::: "memory");
        else             asm volatile("cp.async.wait_group 0;" ::: "memory");
        __syncthreads();

        const uint32_t sA = sb + p * STAGE1;
        const uint32_t sB = sA + TILEB;

#pragma unroll
        for (int kk = 0; kk < 2; kk++) {
            uint32_t bh[4][2];
#pragma unroll
            for (int nf = 0; nf < 4; nf++) {
                const uint32_t off = (b_row + nf * 8) * AROWB + kk * 32 + b_koff;
                ldm_x2(bh[nf], sB + off);
            }
#pragma unroll
            for (int mf = 0; mf < 4; mf++) {
                uint32_t ah[4];
                const uint32_t off = (a_row + mf * 16) * AROWB + kk * 32 + a_koff;
                ldm_x4(ah, sA + off);
#pragma unroll
                for (int nf = 0; nf < 4; nf++) mma16816h(acc[mf][nf], ah, bh[nf]);
            }
        }
        __syncthreads();
        if (i + 2 < NCH) LOAD_CHUNK1(i + 2, p);
        else CP_COMMIT();
    }

    const int g_  = lane >> 2;
    const int tg  = lane & 3;
#pragma unroll
    for (int mf = 0; mf < 4; mf++) {
        const int row = m0 + warp_m * 64 + mf * 16 + g_;
#pragma unroll
        for (int nf = 0; nf < 4; nf++) {
            const int col = n0 + warp_n * 32 + nf * 8 + tg * 2;
            const float b0 = bias[col], b1 = bias[col + 1];
            const float v00 = acc[mf][nf][0] + b0, v01 = acc[mf][nf][1] + b1;
            const float v10 = acc[mf][nf][2] + b0, v11 = acc[mf][nf][3] + b1;
            if (mode == 0) {
                *(float2*)(C + (size_t)row * Ncols + col) = make_float2(v00, v01);
                *(float2*)(C + (size_t)(row + 8) * Ncols + col) = make_float2(v10, v11);
            } else {
                *(uint32_t*)(Ch + (size_t)row * Ncols + col) = packh(v00, v01);
                *(uint32_t*)(Ch + (size_t)(row + 8) * Ncols + col) = packh(v10, v11);
            }
        }
    }
}

// ---------------------------------------------------------------------------
// Flash attention, fp16 1-term: S = Q@Kh, O = Ph@Vh.
// Mq=64, Nk=64, hd=128. V natural + ldmatrix.trans. Smem: Qh,Kh,Vh (51 KB).
// K/V prefetched intra-tile via cp.async. Writes fp16 attn.
// ---------------------------------------------------------------------------
#define FQSTR 272                 // row stride bytes (128 fp16 + 8 pad)
#define FQB   (64 * FQSTR)        // 17408
#define FL_SMEM (3 * FQB)         // 52224

__global__ __launch_bounds__(128) void flash_mma(
    const __half* __restrict__ qh, __half* __restrict__ attnh)
{
    extern __shared__ char smem[];
    const uint32_t sb  = smem_u32(smem);
    const uint32_t sQh = sb;
    const uint32_t sKh = sb + FQB,  sVh = sb + 2 * FQB;

    const int tid = threadIdx.x, wid = tid >> 5, lane = tid & 31;
    const int g = lane >> 2, t = lane & 3;

    int yy = blockIdx.y, b, h, win;
    if (yy < B_ * NFULL) { b = yy / NFULL;  h = yy % NFULL;          win = 0; }
    else { yy -= B_ * NFULL; b = yy / NLOCAL; h = NFULL + yy % NLOCAL; win = 1; }
    const int q0 = blockIdx.x * 64;

    const size_t rb   = (size_t)b * S_ * QKV3 + (size_t)h * HD_;
    const size_t koff = rb + 1536;
    const size_t voff = rb + 3072;

    int kt0 = 0, kt1 = S_ >> 6;
    if (win) {
        kt0 = (q0 >= HWIN) ? ((q0 - HWIN) >> 6) : 0;
        kt1 = min(kt1, ((q0 + 63 + HWIN) >> 6) + 1);
    }

    // Q tile (once) + first K/V tiles
    for (int u = tid; u < 1024; u += 128) {
        const int r = u >> 4, c = u & 15;
        cp16(sQh + r * FQSTR + c * 16, qh + rb + (size_t)(q0 + r) * QKV3 + c * 8);
    }
    {
        const int k0 = kt0 << 6;
        for (int u = tid; u < 1024; u += 128) {
            const int r = u >> 4, c = u & 15;
            cp16(sKh + r * FQSTR + c * 16, qh + koff + (size_t)(k0 + r) * QKV3 + c * 8);
            cp16(sVh + r * FQSTR + c * 16, qh + voff + (size_t)(k0 + r) * QKV3 + c * 8);
        }
    }
    CP_COMMIT();

    float oacc[16][4];
#pragma unroll
    for (int i = 0; i < 16; i++)
#pragma unroll
        for (int j = 0; j < 4; j++) oacc[i][j] = 0.f;
    float m0 = -1e30f, m1 = -1e30f, l0 = 0.f, l1 = 0.f;

    const int a_row  = wid * 16 + (lane & 15);
    const int a_koff = (lane >> 4) * 16;
    const int b_r    = lane & 7;
    const int b_koff = ((lane >> 3) & 1) * 16;
    const int v_row  = lane & 15;          // trans ldmatrix row (key)
    const int row0   = q0 + wid * 16 + g;

    for (int kt = kt0; kt < kt1; kt++) {
        const int k0 = kt << 6;
        asm volatile("cp.async.wait_group 0;" ::: "memory");
        __syncthreads();

        // S = Q @ Kh (1-term)
        float sacc[8][4];
#pragma unroll
        for (int i = 0; i < 8; i++)
#pragma unroll
            for (int j = 0; j < 4; j++) sacc[i][j] = 0.f;
#pragma unroll
        for (int kc = 0; kc < 8; kc++) {
            uint32_t qah[4];
            const uint32_t aoff = a_row * FQSTR + kc * 32 + a_koff;
            ldm_x4(qah, sQh + aoff);
#pragma unroll
            for (int np = 0; np < 4; np++) {
                const int n0f = 2 * np, n1f = n0f + 1;
                uint32_t kbh0[2], kbh1[2];
                const uint32_t bo0 = (n0f * 8 + b_r) * FQSTR + kc * 32 + b_koff;
                const uint32_t bo1 = (n1f * 8 + b_r) * FQSTR + kc * 32 + b_koff;
                ldm_x2(kbh0, sKh + bo0);
                ldm_x2(kbh1, sKh + bo1);
                mma16816h(sacc[n0f], qah, kbh0);
                mma16816h(sacc[n1f], qah, kbh1);
            }
        }
        __syncthreads();   // all warps done reading K smem

        // prefetch next K while softmax+PV run
        if (kt + 1 < kt1) {
            const int kn = (kt + 1) << 6;
            for (int u = tid; u < 1024; u += 128) {
                const int r = u >> 4, c = u & 15;
                cp16(sKh + r * FQSTR + c * 16,
                     qh + koff + (size_t)(kn + r) * QKV3 + c * 8);
            }
            CP_COMMIT();
        }

        // scale + mask + online softmax
        float mt0 = -1e30f, mt1 = -1e30f;
#pragma unroll
        for (int nf = 0; nf < 8; nf++) {
#pragma unroll
            for (int e = 0; e < 4; e++) {
                float v = sacc[nf][e] * SCALE;
                if (win) {
                    const int col = k0 + nf * 8 + 2 * t + (e & 1);
                    const int row = row0 + (e >> 1) * 8;
                    const int dq = row - col;
                    if (dq > HWIN || dq < -HWIN) v = -1e30f;
                }
                sacc[nf][e] = v;
            }
            mt0 = fmaxf(mt0, fmaxf(sacc[nf][0], sacc[nf][1]));
            mt1 = fmaxf(mt1, fmaxf(sacc[nf][2], sacc[nf][3]));
        }
        mt0 = fmaxf(mt0, __shfl_xor_sync(0xffffffffu, mt0, 1));
        mt0 = fmaxf(mt0, __shfl_xor_sync(0xffffffffu, mt0, 2));
        mt1 = fmaxf(mt1, __shfl_xor_sync(0xffffffffu, mt1, 1));
        mt1 = fmaxf(mt1, __shfl_xor_sync(0xffffffffu, mt1, 2));
        const float mn0 = fmaxf(m0, mt0), mn1 = fmaxf(m1, mt1);
        const float al0 = __expf(m0 - mn0), al1 = __expf(m1 - mn1);
        m0 = mn0; m1 = mn1;
        l0 *= al0; l1 *= al1;
#pragma unroll
        for (int dn = 0; dn < 16; dn++) {
            oacc[dn][0] *= al0; oacc[dn][1] *= al0;
            oacc[dn][2] *= al1; oacc[dn][3] *= al1;
        }

        // P = exp(S - m), fp16 in registers
        uint32_t pah[4][4];
#pragma unroll
        for (int c = 0; c < 4; c++) {
            float p0 = __expf(sacc[2 * c][0] - mn0);
            float p1 = __expf(sacc[2 * c][1] - mn0);
            float p2 = __expf(sacc[2 * c][2] - mn1);
            float p3 = __expf(sacc[2 * c][3] - mn1);
            float r0 = __expf(sacc[2 * c + 1][0] - mn0);
            float r1 = __expf(sacc[2 * c + 1][1] - mn0);
            float r2 = __expf(sacc[2 * c + 1][2] - mn1);
            float r3 = __expf(sacc[2 * c + 1][3] - mn1);
            l0 += p0 + p1 + r0 + r1;
            l1 += p2 + p3 + r2 + r3;
            pah[c][0] = packh(p0, p1);
            pah[c][1] = packh(p2, p3);
            pah[c][2] = packh(r0, r1);
            pah[c][3] = packh(r2, r3);
        }

        // O += Ph@Vh; V natural, trans ldmatrix
#pragma unroll
        for (int c = 0; c < 4; c++) {
#pragma unroll
            for (int dp = 0; dp < 8; dp++) {
                const int d0 = 2 * dp, d1 = d0 + 1;
                uint32_t vbh0[2], vbh1[2];
                const uint32_t vo0 = (c * 16 + v_row) * FQSTR + d0 * 16;
                const uint32_t vo1 = (c * 16 + v_row) * FQSTR + d1 * 16;
                ldm_x2t(vbh0, sVh + vo0);
                ldm_x2t(vbh1, sVh + vo1);
                mma16816h(oacc[d0], pah[c], vbh0);
                mma16816h(oacc[d1], pah[c], vbh1);
            }
        }
        __syncthreads();   // all warps done reading V smem

        if (kt + 1 < kt1) {
            const int kn = (kt + 1) << 6;
            for (int u = tid; u < 1024; u += 128) {
                const int r = u >> 4, c = u & 15;
                cp16(sVh + r * FQSTR + c * 16,
                     qh + voff + (size_t)(kn + r) * QKV3 + c * 8);
            }
            CP_COMMIT();
        }
    }

    // finalize: reduce l across t-group, normalize, write fp16
    l0 += __shfl_xor_sync(0xffffffffu, l0, 1);
    l0 += __shfl_xor_sync(0xffffffffu, l0, 2);
    l1 += __shfl_xor_sync(0xffffffffu, l1, 1);
    l1 += __shfl_xor_sync(0xffffffffu, l1, 2);
    const float inv0 = 1.f / l0, inv1 = 1.f / l1;

    const size_t ob0 = ((size_t)b * S_ + row0) * D_ + h * HD_;
    const size_t ob1 = ob0 + 8 * D_;
#pragma unroll
    for (int dn = 0; dn < 16; dn++) {
        const int col = dn * 8 + 2 * t;
        *(uint32_t*)(attnh + ob0 + col) =
            packh(oacc[dn][0] * inv0, oacc[dn][1] * inv0);
        *(uint32_t*)(attnh + ob1 + col) =
            packh(oacc[dn][2] * inv1, oacc[dn][3] * inv1);
    }
}

// ---------------------------------------------------------------------------
// Global heads: fp16 qkv; writes fp16 attn.
// ---------------------------------------------------------------------------
__global__ __launch_bounds__(256) void global_attn(
    const __half* __restrict__ qh, __half* __restrict__ attnh)
{
    const int wip  = threadIdx.x >> 5;
    const int lane = threadIdx.x & 31;
    const int wid  = blockIdx.x * 8 + wip;
    const int q  = wid & (S_ - 1);
    const int hg = (wid >> 11) & 1;
    const int b  = wid >> 12;
    const int h  = NFULL + NLOCAL + hg;

    const size_t base = (size_t)b * S_ * QKV3 + (size_t)h * HD_;
    const size_t qp  = base + (size_t)q * QKV3;
    const size_t kp0 = base + 1536;
    const size_t kp1 = base + 1536 + (size_t)(S_ - 1) * QKV3;
    const size_t vp0 = base + 3072;
    const size_t vp1 = base + 3072 + (size_t)(S_ - 1) * QKV3;

#define RD(off, d) __half2float(qh[(off) + (d)])

    float s0 = 0.f, s1 = 0.f;
#pragma unroll
    for (int c = 0; c < 4; c++) {
        const int d = lane + (c << 5);
        const float qd = RD(qp, d);
        s0 += qd * RD(kp0, d);
        s1 += qd * RD(kp1, d);
    }
#pragma unroll
    for (int o = 16; o > 0; o >>= 1) {
        s0 += __shfl_xor_sync(0xffffffffu, s0, o);
        s1 += __shfl_xor_sync(0xffffffffu, s1, o);
    }
    s0 *= SCALE; s1 *= SCALE;
    const float mx = fmaxf(s0, s1);
    float e0 = __expf(s0 - mx), e1 = __expf(s1 - mx);
    const float inv = 1.f / (e0 + e1);
    e0 *= inv; e1 *= inv;

    const size_t op = ((size_t)b * S_ + q) * D_ + h * HD_;
#pragma unroll
    for (int c = 0; c < 4; c++) {
        const int d = lane + (c << 5);
        attnh[op + d] = __float2half(e0 * RD(vp0, d) + e1 * RD(vp1, d));
    }
#undef RD
}

// ---------------------------------------------------------------------------
extern "C" void kernel_launch(void* const* d_in, const int* in_sizes, int n_in,
                              void* d_out, int out_size)
{
    const float* x    = (const float*)d_in[0];
    const float* Wqkv = (const float*)d_in[1];
    const float* bqkv = (const float*)d_in[2];
    const float* Wout = (const float*)d_in[3];
    const float* bout = (const float*)d_in[4];
    float* out = (float*)d_out;

    __half *qkvh, *X1, *A21, *Wq, *Wo;
    cudaGetSymbolAddress((void**)&qkvh, g_qkvh);
    cudaGetSymbolAddress((void**)&X1,  g_X1);
    cudaGetSymbolAddress((void**)&A21, g_A21);
    cudaGetSymbolAddress((void**)&Wq,  g_Wq);
    cudaGetSymbolAddress((void**)&Wo,  g_Wo);

    cudaFuncSetAttribute(gemm1h,
                         cudaFuncAttributeMaxDynamicSharedMemorySize, GEMM1_SMEM);
    cudaFuncSetAttribute(flash_mma,
                         cudaFuncAttributeMaxDynamicSharedMemorySize, FL_SMEM);

    // Input/weight conversions (all single-term fp16)
    k_cvt_h1<<<(MROWS * KDIM) / 1024, 256>>>(x, X1, MROWS * KDIM);
    k_splitT_h1<<<dim3(QKV3 / 32, KDIM / 32), 256>>>(Wqkv, Wq, KDIM, QKV3);
    k_splitT_h1<<<dim3(D_ / 32, KDIM / 32), 256>>>(Wout, Wo, KDIM, D_);

    // 1) QKV projection (fp16 1-term) -> qkv fp16; dead tiles skipped
    gemm1h<<<dim3(32, MROWS / 128), 256, GEMM1_SMEM>>>(
        X1, Wq, bqkv, nullptr, qkvh, QKV3, 1);
    fix_globalqkv<<<16, 128>>>(x, Wqkv, bqkv, qkvh);

    // 2) Attention (full + windowed fused) + global heads -> fp16 attn
    flash_mma<<<dim3(S_ / 64, B_ * (NFULL + NLOCAL)), 128, FL_SMEM>>>(
        qkvh, A21);
    global_attn<<<(B_ * 2 * S_) / 8, 256>>>(qkvh, A21);

    // 3) Output projection (fp16 1-term) -> fp32 final
    gemm1h<<<dim3(D_ / 128, MROWS / 128), 256, GEMM1_SMEM>>>(
        A21, Wo, bout, out, nullptr, D_, 0);
}